// round 13
// baseline (speedup 1.0000x reference)
#include <cuda_runtime.h>
#include <cuda_fp16.h>
#include <cstdint>
#include <cstddef>

// Problem constants (fixed shapes for Hgnn_17394617548829)
#define N_NODESC 50000
#define N_HEDGESC 5000
#define NNZC 800000
#define IN_C 128
#define D1C 256
#define D2C 64

// Scan chunking: 256 elements per block
#define NBLK_H 20    // ceil(5000/256)
#define NBLK_N 196   // ceil(50000/256)
#define NBLK   216

// ---------------------------------------------------------------------------
// Scratch (static device globals; no allocation anywhere).
// INVARIANT: g_deg / g_cnt are all-zero at kernel_launch entry.
// ---------------------------------------------------------------------------
__device__ __align__(16) __half g_xh  [(size_t)N_NODESC * IN_C];
__device__ __align__(16) __half g_e1h [(size_t)N_HEDGESC * IN_C];
__device__ __align__(16) __half g_a1h [(size_t)N_NODESC * IN_C];
__device__ __align__(16) __half g_hh  [(size_t)N_NODESC * D1C];
__device__ __align__(16) __half g_y2h [(size_t)N_NODESC * D2C];
__device__ __align__(16) __half g_e2h [(size_t)N_HEDGESC * D2C];
__device__ __align__(16) __half g_w1h [(size_t)D1C * IN_C];   // W1^T [256][128]
__device__ __align__(16) __half g_w2h [(size_t)D2C * D1C];    // W2^T [64][256]
__device__ int   g_cnt [N_HEDGESC];
__device__ int   g_deg [N_NODESC];
__device__ int   g_hoff[N_HEDGESC + 1];
__device__ int   g_noff[N_NODESC + 1];
__device__ int   g_hcur[N_HEDGESC];
__device__ int   g_ncur[N_NODESC];
__device__ __align__(16) unsigned short g_hlist[NNZC];        // node ids
__device__ __align__(16) unsigned short g_nlist[NNZC];        // hedge ids
__device__ float g_dinv[N_NODESC];
__device__ float g_binv[N_HEDGESC];
__device__ int   g_part[NBLK];
__device__ int   g_partoff[NBLK];
__device__ int   g_bar0;
__device__ int   g_bar1;

// ---------------------------------------------------------------------------
// fp16 helpers
// ---------------------------------------------------------------------------
__device__ __forceinline__ __half2 h2(unsigned u) {
    return *reinterpret_cast<__half2*>(&u);
}

// accumulate 8 halves (uint4) into two float4s
__device__ __forceinline__ void acc_h4(float4& a, float4& b, uint4 u) {
    float2 f0 = __half22float2(h2(u.x));
    float2 f1 = __half22float2(h2(u.y));
    float2 f2 = __half22float2(h2(u.z));
    float2 f3 = __half22float2(h2(u.w));
    a.x += f0.x; a.y += f0.y; a.z += f1.x; a.w += f1.y;
    b.x += f2.x; b.y += f2.y; b.z += f3.x; b.w += f3.y;
}

// pairwise HADD2 of two 8-half rows, then fp32 accumulate
__device__ __forceinline__ void acc_pair4(float4& a, float4& b, uint4 u, uint4 v) {
    __half2 s0 = __hadd2(h2(u.x), h2(v.x));
    __half2 s1 = __hadd2(h2(u.y), h2(v.y));
    __half2 s2 = __hadd2(h2(u.z), h2(v.z));
    __half2 s3 = __hadd2(h2(u.w), h2(v.w));
    float2 f0 = __half22float2(s0);
    float2 f1 = __half22float2(s1);
    float2 f2 = __half22float2(s2);
    float2 f3 = __half22float2(s3);
    a.x += f0.x; a.y += f0.y; a.z += f1.x; a.w += f1.y;
    b.x += f2.x; b.y += f2.y; b.z += f3.x; b.w += f3.y;
}

__device__ __forceinline__ uint2 pack_h2(float x, float y, float z, float w) {
    __half2 h0 = __floats2half2_rn(x, y);
    __half2 h1 = __floats2half2_rn(z, w);
    uint2 u;
    u.x = *reinterpret_cast<unsigned*>(&h0);
    u.y = *reinterpret_cast<unsigned*>(&h1);
    return u;
}

__device__ __forceinline__ uint4 pack_h4(float4 a, float4 b) {
    uint2 lo = pack_h2(a.x, a.y, a.z, a.w);
    uint2 hi = pack_h2(b.x, b.y, b.z, b.w);
    uint4 u; u.x = lo.x; u.y = lo.y; u.z = hi.x; u.w = hi.y;
    return u;
}

// combine sub-halves: add partner lane (xor dist) values into a0/a1
__device__ __forceinline__ void shfl_combine(float4& a0, float4& a1, int dist) {
    a0.x += __shfl_xor_sync(0xffffffffu, a0.x, dist);
    a0.y += __shfl_xor_sync(0xffffffffu, a0.y, dist);
    a0.z += __shfl_xor_sync(0xffffffffu, a0.z, dist);
    a0.w += __shfl_xor_sync(0xffffffffu, a0.w, dist);
    a1.x += __shfl_xor_sync(0xffffffffu, a1.x, dist);
    a1.y += __shfl_xor_sync(0xffffffffu, a1.y, dist);
    a1.z += __shfl_xor_sync(0xffffffffu, a1.z, dist);
    a1.w += __shfl_xor_sync(0xffffffffu, a1.w, dist);
}

// ---------------------------------------------------------------------------
// 0. FUSED: degree histograms (fire-and-forget REDs) + fp16 conversions +
//    grid-barrier reset.
// ---------------------------------------------------------------------------
__global__ void __launch_bounds__(256) cvt_k(const float* __restrict__ x,
                                             const float* __restrict__ W1,
                                             const float* __restrict__ W2,
                                             const int* __restrict__ ni,
                                             const int* __restrict__ hi) {
    int i = blockIdx.x * blockDim.x + threadIdx.x;
    int stride = gridDim.x * blockDim.x;
    if (i == 0) { g_bar0 = 0; g_bar1 = 0; }

    for (int j = i; j < NNZC / 2; j += stride) {
        int2 nn = *reinterpret_cast<const int2*>(ni + 2 * j);
        int2 hh = *reinterpret_cast<const int2*>(hi + 2 * j);
        atomicAdd(&g_deg[nn.x], 1);
        atomicAdd(&g_deg[nn.y], 1);
        atomicAdd(&g_cnt[hh.x], 1);
        atomicAdd(&g_cnt[hh.y], 1);
    }

    const float4* x4 = reinterpret_cast<const float4*>(x);
    uint2* xh2 = reinterpret_cast<uint2*>(g_xh);
    for (int j = i; j < N_NODESC * IN_C / 4; j += stride) {
        float4 v = x4[j];
        xh2[j] = pack_h2(v.x, v.y, v.z, v.w);
    }
    for (int j = i; j < D1C * IN_C; j += stride) {
        int n = j / IN_C, k = j % IN_C;
        g_w1h[j] = __float2half(W1[(size_t)k * D1C + n]);
    }
    for (int j = i; j < D2C * D1C; j += stride) {
        int n = j / D1C, k = j % D1C;
        g_w2h[j] = __float2half(W2[(size_t)k * D2C + n]);
    }
}

// ---------------------------------------------------------------------------
// 1. fused segmented exclusive scan (grid barrier; phase 2 in block-0 smem)
// ---------------------------------------------------------------------------
__global__ void __launch_bounds__(256) scan_k() {
    __shared__ int sh[256];
    __shared__ int shp[NBLK];
    const int b   = blockIdx.x;
    const int tid = threadIdx.x;
    const int* src; int* off; int* cur; float* inv;
    int idx, n;
    if (b < NBLK_H) {
        src = g_cnt; off = g_hoff; cur = g_hcur; inv = g_binv;
        idx = b * 256 + tid; n = N_HEDGESC;
    } else {
        src = g_deg; off = g_noff; cur = g_ncur; inv = g_dinv;
        idx = (b - NBLK_H) * 256 + tid; n = N_NODESC;
    }
    int v = (idx < n) ? src[idx] : 0;

    sh[tid] = v;
    __syncthreads();
    for (int d = 1; d < 256; d <<= 1) {
        int t = (tid >= d) ? sh[tid - d] : 0;
        __syncthreads();
        sh[tid] += t;
        __syncthreads();
    }
    int incl = sh[tid];
    if (tid == 255) {
        g_part[b] = incl;
        __threadfence();
        atomicAdd(&g_bar0, 1);
    }

    if (b == 0) {
        if (tid == 0) {
            while (atomicAdd(&g_bar0, 0) < NBLK) __nanosleep(32);
        }
        __syncthreads();
        __threadfence();
        if (tid < NBLK) shp[tid] = g_part[tid];
        __syncthreads();
        if (tid == 0) {
            int run = 0;
            for (int i = 0; i < NBLK_H; i++) { int c = shp[i]; shp[i] = run; run += c; }
            run = 0;
            for (int i = NBLK_H; i < NBLK; i++) { int c = shp[i]; shp[i] = run; run += c; }
        }
        __syncthreads();
        if (tid < NBLK) g_partoff[tid] = shp[tid];
        __threadfence();
        __syncthreads();
        if (tid == 0) atomicExch(&g_bar1, 1);
    }
    if (tid == 0) {
        while (atomicAdd(&g_bar1, 0) == 0) __nanosleep(32);
    }
    __syncthreads();
    __threadfence();

    if (idx < n) {
        int excl = incl - v + g_partoff[b];
        off[idx] = excl;
        cur[idx] = excl;
        inv[idx] = (v > 0) ? 1.0f / (float)v : 0.0f;
    }
    if (b == 0 && tid == 0) {
        g_hoff[N_HEDGESC] = NNZC;
        g_noff[N_NODESC]  = NNZC;
    }
}

// ---------------------------------------------------------------------------
// 2. scatter edges into both CSR member lists (2 edges/thread, u16 payloads)
// ---------------------------------------------------------------------------
__global__ void __launch_bounds__(256) build_k(const int* __restrict__ ni,
                                               const int* __restrict__ hi) {
    int i = blockIdx.x * blockDim.x + threadIdx.x;
    if (2 * i >= NNZC) return;
    int2 nn = *reinterpret_cast<const int2*>(ni + 2 * i);
    int2 hh = *reinterpret_cast<const int2*>(hi + 2 * i);
    int p0 = atomicAdd(&g_hcur[hh.x], 1);
    int p1 = atomicAdd(&g_hcur[hh.y], 1);
    int q0 = atomicAdd(&g_ncur[nn.x], 1);
    int q1 = atomicAdd(&g_ncur[nn.y], 1);
    g_hlist[p0] = (unsigned short)nn.x;
    g_hlist[p1] = (unsigned short)nn.y;
    g_nlist[q0] = (unsigned short)hh.x;
    g_nlist[q1] = (unsigned short)hh.y;
}

// ---------------------------------------------------------------------------
// Gather kernels. fp16 payload, LDG.128 per lane, lane-split edge ILP
// (sub-half processes alternating edges; shfl_xor combine at segment end),
// pairwise HADD2, fp32 accumulation.
// ---------------------------------------------------------------------------

// e1h[h] = binv[h] * sum x_h[n]   (128 ch; 2 warps/hedge; 16 lanes x uint4)
__global__ void __launch_bounds__(256) n2h1_k() {
    __shared__ float sm[4][IN_C];
    const int hloc = threadIdx.x >> 6;
    const int half = (threadIdx.x >> 5) & 1;
    const int lane = threadIdx.x & 31;
    const int sub  = lane >> 4;         // which edge of the pair
    const int c8   = lane & 15;         // 8-channel chunk
    const int h = blockIdx.x * 4 + hloc;   // grid exact: 1250*4
    const int s = g_hoff[h], e = g_hoff[h + 1];
    const int mid = (s + e) >> 1;
    int j   = half ? mid : s;
    int end = half ? e   : mid;

    float4 a0 = make_float4(0.f, 0.f, 0.f, 0.f), a1 = a0;
    for (; j < end && (j & 3); j++) {
        if (sub == 0) {
            int n0 = __ldg(g_hlist + j);
            uint4 u = __ldg(reinterpret_cast<const uint4*>(g_xh + n0 * IN_C) + c8);
            acc_h4(a0, a1, u);
        }
    }
    for (; j + 4 <= end; j += 4) {
        uint2 idx = __ldg(reinterpret_cast<const uint2*>(g_hlist + j));  // 4 ids
        int na = sub ? (int)(idx.x >> 16) : (int)(idx.x & 0xFFFF);   // j / j+1
        int nb = sub ? (int)(idx.y >> 16) : (int)(idx.y & 0xFFFF);   // j+2 / j+3
        uint4 ua = __ldg(reinterpret_cast<const uint4*>(g_xh + na * IN_C) + c8);
        uint4 ub = __ldg(reinterpret_cast<const uint4*>(g_xh + nb * IN_C) + c8);
        acc_pair4(a0, a1, ua, ub);
    }
    for (; j < end; j++) {
        if (sub == 0) {
            int n0 = __ldg(g_hlist + j);
            uint4 u = __ldg(reinterpret_cast<const uint4*>(g_xh + n0 * IN_C) + c8);
            acc_h4(a0, a1, u);
        }
    }
    shfl_combine(a0, a1, 16);           // merge sub halves
    if (half == 1 && sub == 0) {
        *reinterpret_cast<float4*>(&sm[hloc][c8 * 8])     = a0;
        *reinterpret_cast<float4*>(&sm[hloc][c8 * 8 + 4]) = a1;
    }
    __syncthreads();
    if (half == 0 && sub == 0) {
        float4 o0 = *reinterpret_cast<const float4*>(&sm[hloc][c8 * 8]);
        float4 o1 = *reinterpret_cast<const float4*>(&sm[hloc][c8 * 8 + 4]);
        float bi = g_binv[h];
        float4 r0, r1;
        r0.x = (a0.x + o0.x) * bi; r0.y = (a0.y + o0.y) * bi;
        r0.z = (a0.z + o0.z) * bi; r0.w = (a0.w + o0.w) * bi;
        r1.x = (a1.x + o1.x) * bi; r1.y = (a1.y + o1.y) * bi;
        r1.z = (a1.z + o1.z) * bi; r1.w = (a1.w + o1.w) * bi;
        reinterpret_cast<uint4*>(g_e1h + h * IN_C)[c8] = pack_h4(r0, r1);
    }
}

// a1h[n] = dinv[n] * sum e1h[h]   (128 ch; warp/node; 16 lanes x uint4)
__global__ void __launch_bounds__(256) h2n1_k() {
    int w = blockIdx.x * 8 + (threadIdx.x >> 5);
    if (w >= N_NODESC) return;
    int lane = threadIdx.x & 31;
    int sub = lane >> 4, c8 = lane & 15;
    int j = g_noff[w], end = g_noff[w + 1];
    float4 a0 = make_float4(0.f, 0.f, 0.f, 0.f), a1 = a0;
    for (; j < end && (j & 3); j++) {
        if (sub == 0) {
            int h0 = __ldg(g_nlist + j);
            uint4 u = __ldg(reinterpret_cast<const uint4*>(g_e1h + h0 * IN_C) + c8);
            acc_h4(a0, a1, u);
        }
    }
    for (; j + 4 <= end; j += 4) {
        uint2 idx = __ldg(reinterpret_cast<const uint2*>(g_nlist + j));
        int ha = sub ? (int)(idx.x >> 16) : (int)(idx.x & 0xFFFF);
        int hb = sub ? (int)(idx.y >> 16) : (int)(idx.y & 0xFFFF);
        uint4 ua = __ldg(reinterpret_cast<const uint4*>(g_e1h + ha * IN_C) + c8);
        uint4 ub = __ldg(reinterpret_cast<const uint4*>(g_e1h + hb * IN_C) + c8);
        acc_pair4(a0, a1, ua, ub);
    }
    for (; j < end; j++) {
        if (sub == 0) {
            int h0 = __ldg(g_nlist + j);
            uint4 u = __ldg(reinterpret_cast<const uint4*>(g_e1h + h0 * IN_C) + c8);
            acc_h4(a0, a1, u);
        }
    }
    shfl_combine(a0, a1, 16);
    if (sub == 0) {
        float di = g_dinv[w];
        float4 r0, r1;
        r0.x = a0.x * di; r0.y = a0.y * di; r0.z = a0.z * di; r0.w = a0.w * di;
        r1.x = a1.x * di; r1.y = a1.y * di; r1.z = a1.z * di; r1.w = a1.w * di;
        reinterpret_cast<uint4*>(g_a1h + w * IN_C)[c8] = pack_h4(r0, r1);
    }
}

// e2h[h] = binv[h] * sum y2h[n]   (64 ch; 2 x 16-lane groups/hedge; 8 x uint4)
__global__ void __launch_bounds__(256) n2h2_k() {
    __shared__ float sm[8][D2C];
    const int hloc = threadIdx.x >> 5;
    const int half = (threadIdx.x >> 4) & 1;
    const int l16  = threadIdx.x & 15;
    const int sub  = l16 >> 3;
    const int c8   = l16 & 7;
    const int h = blockIdx.x * 8 + hloc;   // grid exact: 625*8
    const int s = g_hoff[h], e = g_hoff[h + 1];
    const int mid = (s + e) >> 1;
    int j   = half ? mid : s;
    int end = half ? e   : mid;

    float4 a0 = make_float4(0.f, 0.f, 0.f, 0.f), a1 = a0;
    for (; j < end && (j & 3); j++) {
        if (sub == 0) {
            int n0 = __ldg(g_hlist + j);
            uint4 u = __ldg(reinterpret_cast<const uint4*>(g_y2h + n0 * D2C) + c8);
            acc_h4(a0, a1, u);
        }
    }
    for (; j + 4 <= end; j += 4) {
        uint2 idx = __ldg(reinterpret_cast<const uint2*>(g_hlist + j));
        int na = sub ? (int)(idx.x >> 16) : (int)(idx.x & 0xFFFF);
        int nb = sub ? (int)(idx.y >> 16) : (int)(idx.y & 0xFFFF);
        uint4 ua = __ldg(reinterpret_cast<const uint4*>(g_y2h + na * D2C) + c8);
        uint4 ub = __ldg(reinterpret_cast<const uint4*>(g_y2h + nb * D2C) + c8);
        acc_pair4(a0, a1, ua, ub);
    }
    for (; j < end; j++) {
        if (sub == 0) {
            int n0 = __ldg(g_hlist + j);
            uint4 u = __ldg(reinterpret_cast<const uint4*>(g_y2h + n0 * D2C) + c8);
            acc_h4(a0, a1, u);
        }
    }
    shfl_combine(a0, a1, 8);            // merge sub halves within 16-lane group
    if (half == 1 && sub == 0) {
        *reinterpret_cast<float4*>(&sm[hloc][c8 * 8])     = a0;
        *reinterpret_cast<float4*>(&sm[hloc][c8 * 8 + 4]) = a1;
    }
    __syncthreads();
    if (half == 0 && sub == 0) {
        float4 o0 = *reinterpret_cast<const float4*>(&sm[hloc][c8 * 8]);
        float4 o1 = *reinterpret_cast<const float4*>(&sm[hloc][c8 * 8 + 4]);
        float bi = g_binv[h];
        float4 r0, r1;
        r0.x = (a0.x + o0.x) * bi; r0.y = (a0.y + o0.y) * bi;
        r0.z = (a0.z + o0.z) * bi; r0.w = (a0.w + o0.w) * bi;
        r1.x = (a1.x + o1.x) * bi; r1.y = (a1.y + o1.y) * bi;
        r1.z = (a1.z + o1.z) * bi; r1.w = (a1.w + o1.w) * bi;
        reinterpret_cast<uint4*>(g_e2h + h * D2C)[c8] = pack_h4(r0, r1);
    }
}

// out[n] = relu(dinv[n] * sum e2h[h] + b2); tail restores zero-counter invariant
__global__ void __launch_bounds__(256) h2n2_k(const float* __restrict__ b2,
                                              float* __restrict__ out) {
    int g = blockIdx.x * 16 + (threadIdx.x >> 4);
    if (g < N_NODESC) {
        int l16 = threadIdx.x & 15;
        int sub = l16 >> 3, c8 = l16 & 7;
        int j = g_noff[g], end = g_noff[g + 1];
        float4 a0 = make_float4(0.f, 0.f, 0.f, 0.f), a1 = a0;
        for (; j < end && (j & 3); j++) {
            if (sub == 0) {
                int h0 = __ldg(g_nlist + j);
                uint4 u = __ldg(reinterpret_cast<const uint4*>(g_e2h + h0 * D2C) + c8);
                acc_h4(a0, a1, u);
            }
        }
        for (; j + 4 <= end; j += 4) {
            uint2 idx = __ldg(reinterpret_cast<const uint2*>(g_nlist + j));
            int ha = sub ? (int)(idx.x >> 16) : (int)(idx.x & 0xFFFF);
            int hb = sub ? (int)(idx.y >> 16) : (int)(idx.y & 0xFFFF);
            uint4 ua = __ldg(reinterpret_cast<const uint4*>(g_e2h + ha * D2C) + c8);
            uint4 ub = __ldg(reinterpret_cast<const uint4*>(g_e2h + hb * D2C) + c8);
            acc_pair4(a0, a1, ua, ub);
        }
        for (; j < end; j++) {
            if (sub == 0) {
                int h0 = __ldg(g_nlist + j);
                uint4 u = __ldg(reinterpret_cast<const uint4*>(g_e2h + h0 * D2C) + c8);
                acc_h4(a0, a1, u);
            }
        }
        shfl_combine(a0, a1, 8);
        if (sub == 0) {
            float di = g_dinv[g];
            float4 b0 = __ldg(reinterpret_cast<const float4*>(b2) + 2 * c8);
            float4 b1 = __ldg(reinterpret_cast<const float4*>(b2) + 2 * c8 + 1);
            float4 r0, r1;
            r0.x = fmaxf(fmaf(a0.x, di, b0.x), 0.f);
            r0.y = fmaxf(fmaf(a0.y, di, b0.y), 0.f);
            r0.z = fmaxf(fmaf(a0.z, di, b0.z), 0.f);
            r0.w = fmaxf(fmaf(a0.w, di, b0.w), 0.f);
            r1.x = fmaxf(fmaf(a1.x, di, b1.x), 0.f);
            r1.y = fmaxf(fmaf(a1.y, di, b1.y), 0.f);
            r1.z = fmaxf(fmaf(a1.z, di, b1.z), 0.f);
            r1.w = fmaxf(fmaf(a1.w, di, b1.w), 0.f);
            reinterpret_cast<float4*>(out + g * D2C)[2 * c8]     = r0;
            reinterpret_cast<float4*>(out + g * D2C)[2 * c8 + 1] = r1;
        }
    }
    // restore invariant: counters zero for next launch
    int t = blockIdx.x * blockDim.x + threadIdx.x;
    int stride = gridDim.x * blockDim.x;
    for (int j = t; j < N_NODESC; j += stride) g_deg[j] = 0;
    for (int j = t; j < N_HEDGESC; j += stride) g_cnt[j] = 0;
}

// ---------------------------------------------------------------------------
// fp16 tensor-core GEMM (R6 verified).
// ---------------------------------------------------------------------------
__device__ __forceinline__ void mma_f16(float& d0, float& d1, float& d2, float& d3,
                                        uint32_t a0, uint32_t a1, uint32_t a2, uint32_t a3,
                                        uint32_t b0, uint32_t b1) {
    asm volatile(
        "mma.sync.aligned.m16n8k16.row.col.f32.f16.f16.f32 "
        "{%0,%1,%2,%3}, {%4,%5,%6,%7}, {%8,%9}, {%0,%1,%2,%3};"
        : "+f"(d0), "+f"(d1), "+f"(d2), "+f"(d3)
        : "r"(a0), "r"(a1), "r"(a2), "r"(a3), "r"(b0), "r"(b1));
}

template <int BM, int BN, int BK, int WARPS_M, int WARPS_N, bool EPI>
__device__ __forceinline__ void gemm_f16_body(const __half* __restrict__ A,
                                              const __half* __restrict__ Bt,
                                              const float* __restrict__ bias,
                                              __half* __restrict__ C,
                                              int M, int N, int K) {
    constexpr int THREADS = WARPS_M * WARPS_N * 32;
    constexpr int WM = BM / WARPS_M;
    constexpr int WN = BN / WARPS_N;
    constexpr int MI = WM / 16;
    constexpr int NI = WN / 8;
    constexpr int PAD = 8;
    constexpr int AV = (BM * BK / 8) / THREADS;
    constexpr int BV = (BN * BK / 8) / THREADS;

    __shared__ __align__(16) __half As[BM][BK + PAD];
    __shared__ __align__(16) __half Bs[BN][BK + PAD];

    const int tid  = threadIdx.x;
    const int warp = tid >> 5;
    const int lane = tid & 31;
    const int wm   = warp / WARPS_N;
    const int wn   = warp % WARPS_N;
    const int row0 = blockIdx.y * BM;
    const int col0 = blockIdx.x * BN;
    const int lq   = lane >> 2;
    const int lr   = lane & 3;

    float acc[MI][NI][4];
#pragma unroll
    for (int i = 0; i < MI; i++)
#pragma unroll
        for (int j = 0; j < NI; j++)
#pragma unroll
            for (int c = 0; c < 4; c++) acc[i][j][c] = 0.f;

    for (int kt = 0; kt < K; kt += BK) {
#pragma unroll
        for (int i = 0; i < AV; i++) {
            int idx = tid + i * THREADS;
            int m   = idx / (BK / 8);
            int kc  = (idx % (BK / 8)) * 8;
            int grow = row0 + m;
            uint4 v = make_uint4(0, 0, 0, 0);
            if (grow < M)
                v = __ldg(reinterpret_cast<const uint4*>(A + (size_t)grow * K + kt + kc));
            *reinterpret_cast<uint4*>(&As[m][kc]) = v;
        }
#pragma unroll
        for (int i = 0; i < BV; i++) {
            int idx = tid + i * THREADS;
            int n   = idx / (BK / 8);
            int kc  = (idx % (BK / 8)) * 8;
            uint4 v = __ldg(reinterpret_cast<const uint4*>(Bt + (size_t)(col0 + n) * K + kt + kc));
            *reinterpret_cast<uint4*>(&Bs[n][kc]) = v;
        }
        __syncthreads();

#pragma unroll
        for (int ks = 0; ks < BK; ks += 16) {
            uint32_t af[MI][4];
            uint32_t bf[NI][2];
#pragma unroll
            for (int i = 0; i < MI; i++) {
                int m0 = wm * WM + i * 16;
                af[i][0] = *reinterpret_cast<const uint32_t*>(&As[m0 + lq    ][ks + 2 * lr    ]);
                af[i][1] = *reinterpret_cast<const uint32_t*>(&As[m0 + lq + 8][ks + 2 * lr    ]);
                af[i][2] = *reinterpret_cast<const uint32_t*>(&As[m0 + lq    ][ks + 2 * lr + 8]);
                af[i][3] = *reinterpret_cast<const uint32_t*>(&As[m0 + lq + 8][ks + 2 * lr + 8]);
            }
#pragma unroll
            for (int j = 0; j < NI; j++) {
                int n0 = wn * WN + j * 8;
                bf[j][0] = *reinterpret_cast<const uint32_t*>(&Bs[n0 + lq][ks + 2 * lr    ]);
                bf[j][1] = *reinterpret_cast<const uint32_t*>(&Bs[n0 + lq][ks + 2 * lr + 8]);
            }
#pragma unroll
            for (int i = 0; i < MI; i++)
#pragma unroll
                for (int j = 0; j < NI; j++)
                    mma_f16(acc[i][j][0], acc[i][j][1], acc[i][j][2], acc[i][j][3],
                            af[i][0], af[i][1], af[i][2], af[i][3],
                            bf[j][0], bf[j][1]);
        }
        __syncthreads();
    }

#pragma unroll
    for (int i = 0; i < MI; i++) {
#pragma unroll
        for (int j = 0; j < NI; j++) {
            int row = row0 + wm * WM + i * 16 + lq;
            int col = col0 + wn * WN + j * 8 + 2 * lr;
            float2 v0 = make_float2(acc[i][j][0], acc[i][j][1]);
            float2 v1 = make_float2(acc[i][j][2], acc[i][j][3]);
            if (EPI) {
                float b0 = bias[col], b1 = bias[col + 1];
                v0.x = fmaxf(v0.x + b0, 0.f);
                v0.y = fmaxf(v0.y + b1, 0.f);
                v1.x = fmaxf(v1.x + b0, 0.f);
                v1.y = fmaxf(v1.y + b1, 0.f);
            }
            if (row < M)
                *reinterpret_cast<__half2*>(&C[(size_t)row * N + col]) =
                    __floats2half2_rn(v0.x, v0.y);
            if (row + 8 < M)
                *reinterpret_cast<__half2*>(&C[(size_t)(row + 8) * N + col]) =
                    __floats2half2_rn(v1.x, v1.y);
        }
    }
}

// GEMM1: g_hh = relu(g_a1h @ W1 + b1)   [50000x128]@[128x256]
__global__ void __launch_bounds__(256) gemm1_k(const float* __restrict__ b1) {
    gemm_f16_body<128, 128, 32, 2, 4, true>(g_a1h, g_w1h, b1, g_hh, N_NODESC, D1C, IN_C);
}

// GEMM2: g_y2h = g_hh @ W2   [50000x256]@[256x64]
__global__ void __launch_bounds__(256) gemm2_k() {
    gemm_f16_body<128, 64, 32, 4, 2, false>(g_hh, g_w2h, nullptr, g_y2h, N_NODESC, D2C, D1C);
}

// ---------------------------------------------------------------------------
// Launch (9 kernels)
// ---------------------------------------------------------------------------
extern "C" void kernel_launch(void* const* d_in, const int* in_sizes, int n_in,
                              void* d_out, int out_size) {
    const float* x    = (const float*)d_in[0];
    const int*   edge = (const int*)d_in[1];
    const float* W1   = (const float*)d_in[2];
    const float* b1   = (const float*)d_in[3];
    const float* W2   = (const float*)d_in[4];
    const float* b2   = (const float*)d_in[5];
    float*       out  = (float*)d_out;

    const int* ni = edge;          // edge[0] = node_idx
    const int* hi = edge + NNZC;   // edge[1] = hedge_idx

    // fused hist + conversions + barrier reset; then scan + scatter
    cvt_k<<<1024, 256>>>(x, W1, W2, ni, hi);
    scan_k<<<NBLK, 256>>>();
    build_k<<<(NNZC / 2 + 255) / 256, 256>>>(ni, hi);

    // Layer 1 aggregation at 128 channels (split hedge-side gather, LDG.128)
    n2h1_k<<<N_HEDGESC / 4, 256>>>();
    h2n1_k<<<(N_NODESC + 7) / 8, 256>>>();

    // h = relu(agg1 @ W1 + b1) ; y2 = h @ W2   (fp16 tensor cores)
    {
        dim3 g1(D1C / 128, (N_NODESC + 127) / 128);
        gemm1_k<<<g1, 256>>>(b1);
        dim3 g2(D2C / 64, (N_NODESC + 127) / 128);
        gemm2_k<<<g2, 256>>>();
    }

    // Layer 2 aggregation at 64 channels (split hedge-side gather) + epilogue
    n2h2_k<<<N_HEDGESC / 8, 256>>>();
    h2n2_k<<<(N_NODESC + 15) / 16, 256>>>(b2, out);
}

// round 14
// speedup vs baseline: 1.0521x; 1.0521x over previous
#include <cuda_runtime.h>
#include <cuda_fp16.h>
#include <cstdint>
#include <cstddef>

// Problem constants (fixed shapes for Hgnn_17394617548829)
#define N_NODESC 50000
#define N_HEDGESC 5000
#define NNZC 800000
#define IN_C 128
#define D1C 256
#define D2C 64

// Scan chunking: 256 elements per block
#define NBLK_H 20    // ceil(5000/256)
#define NBLK_N 196   // ceil(50000/256)
#define NBLK   216

// ---------------------------------------------------------------------------
// Scratch (static device globals; no allocation anywhere).
// INVARIANT: g_deg / g_cnt are all-zero at kernel_launch entry.
// ---------------------------------------------------------------------------
__device__ __align__(16) __half g_xh  [(size_t)N_NODESC * IN_C];   // 12.8 MB
__device__ __align__(16) __half g_e1h [(size_t)N_HEDGESC * IN_C];  // 1.28 MB
__device__ __align__(16) __half g_a1h [(size_t)N_NODESC * IN_C];   // 12.8 MB
__device__ __align__(16) __half g_y2h [(size_t)N_NODESC * D2C];    // 6.4 MB
__device__ __align__(16) __half g_e2h [(size_t)N_HEDGESC * D2C];   // 0.64 MB
__device__ __align__(16) __half g_w1h [(size_t)D1C * IN_C];        // W1^T [256][128]
__device__ __align__(16) __half g_w2h [(size_t)D2C * D1C];         // W2^T [64][256]
__device__ int   g_cnt [N_HEDGESC];
__device__ int   g_deg [N_NODESC];
__device__ int   g_hoff[N_HEDGESC + 1];
__device__ int   g_noff[N_NODESC + 1];
__device__ int   g_hcur[N_HEDGESC];
__device__ int   g_ncur[N_NODESC];
__device__ __align__(16) unsigned short g_hlist[NNZC];             // node ids
__device__ __align__(16) unsigned short g_nlist[NNZC];             // hedge ids
__device__ float g_dinv[N_NODESC];
__device__ float g_binv[N_HEDGESC];
__device__ int   g_part[NBLK];
__device__ int   g_partoff[NBLK];
__device__ int   g_bar0;
__device__ int   g_bar1;

// ---------------------------------------------------------------------------
// fp16 helpers (R11-proven)
// ---------------------------------------------------------------------------
__device__ __forceinline__ void acc_h2(float4& a, uint2 u) {
    float2 f0 = __half22float2(*reinterpret_cast<__half2*>(&u.x));
    float2 f1 = __half22float2(*reinterpret_cast<__half2*>(&u.y));
    a.x += f0.x; a.y += f0.y; a.z += f1.x; a.w += f1.y;
}

__device__ __forceinline__ void acc_pair(float4& a, uint2 u0, uint2 u1) {
    __half2 sx = __hadd2(*reinterpret_cast<__half2*>(&u0.x),
                         *reinterpret_cast<__half2*>(&u1.x));
    __half2 sy = __hadd2(*reinterpret_cast<__half2*>(&u0.y),
                         *reinterpret_cast<__half2*>(&u1.y));
    float2 fx = __half22float2(sx);
    float2 fy = __half22float2(sy);
    a.x += fx.x; a.y += fx.y; a.z += fy.x; a.w += fy.y;
}

__device__ __forceinline__ uint2 pack_h2(float x, float y, float z, float w) {
    __half2 h0 = __floats2half2_rn(x, y);
    __half2 h1 = __floats2half2_rn(z, w);
    uint2 u;
    u.x = *reinterpret_cast<unsigned*>(&h0);
    u.y = *reinterpret_cast<unsigned*>(&h1);
    return u;
}

// ---------------------------------------------------------------------------
// 0. FUSED: degree histograms + fp16 conversions + grid-barrier reset
// ---------------------------------------------------------------------------
__global__ void __launch_bounds__(256) cvt_k(const float* __restrict__ x,
                                             const float* __restrict__ W1,
                                             const float* __restrict__ W2,
                                             const int* __restrict__ ni,
                                             const int* __restrict__ hi) {
    int i = blockIdx.x * blockDim.x + threadIdx.x;
    int stride = gridDim.x * blockDim.x;
    if (i == 0) { g_bar0 = 0; g_bar1 = 0; }

    for (int j = i; j < NNZC / 2; j += stride) {
        int2 nn = *reinterpret_cast<const int2*>(ni + 2 * j);
        int2 hh = *reinterpret_cast<const int2*>(hi + 2 * j);
        atomicAdd(&g_deg[nn.x], 1);
        atomicAdd(&g_deg[nn.y], 1);
        atomicAdd(&g_cnt[hh.x], 1);
        atomicAdd(&g_cnt[hh.y], 1);
    }

    const float4* x4 = reinterpret_cast<const float4*>(x);
    uint2* xh2 = reinterpret_cast<uint2*>(g_xh);
    for (int j = i; j < N_NODESC * IN_C / 4; j += stride) {
        float4 v = x4[j];
        xh2[j] = pack_h2(v.x, v.y, v.z, v.w);
    }
    for (int j = i; j < D1C * IN_C; j += stride) {
        int n = j / IN_C, k = j % IN_C;
        g_w1h[j] = __float2half(W1[(size_t)k * D1C + n]);
    }
    for (int j = i; j < D2C * D1C; j += stride) {
        int n = j / D1C, k = j % D1C;
        g_w2h[j] = __float2half(W2[(size_t)k * D2C + n]);
    }
}

// ---------------------------------------------------------------------------
// 1. fused segmented exclusive scan (grid barrier; phase 2 in block-0 smem)
// ---------------------------------------------------------------------------
__global__ void __launch_bounds__(256) scan_k() {
    __shared__ int sh[256];
    __shared__ int shp[NBLK];
    const int b   = blockIdx.x;
    const int tid = threadIdx.x;
    const int* src; int* off; int* cur; float* inv;
    int idx, n;
    if (b < NBLK_H) {
        src = g_cnt; off = g_hoff; cur = g_hcur; inv = g_binv;
        idx = b * 256 + tid; n = N_HEDGESC;
    } else {
        src = g_deg; off = g_noff; cur = g_ncur; inv = g_dinv;
        idx = (b - NBLK_H) * 256 + tid; n = N_NODESC;
    }
    int v = (idx < n) ? src[idx] : 0;

    sh[tid] = v;
    __syncthreads();
    for (int d = 1; d < 256; d <<= 1) {
        int t = (tid >= d) ? sh[tid - d] : 0;
        __syncthreads();
        sh[tid] += t;
        __syncthreads();
    }
    int incl = sh[tid];
    if (tid == 255) {
        g_part[b] = incl;
        __threadfence();
        atomicAdd(&g_bar0, 1);
    }

    if (b == 0) {
        if (tid == 0) {
            while (atomicAdd(&g_bar0, 0) < NBLK) __nanosleep(32);
        }
        __syncthreads();
        __threadfence();
        if (tid < NBLK) shp[tid] = g_part[tid];
        __syncthreads();
        if (tid == 0) {
            int run = 0;
            for (int i = 0; i < NBLK_H; i++) { int c = shp[i]; shp[i] = run; run += c; }
            run = 0;
            for (int i = NBLK_H; i < NBLK; i++) { int c = shp[i]; shp[i] = run; run += c; }
        }
        __syncthreads();
        if (tid < NBLK) g_partoff[tid] = shp[tid];
        __threadfence();
        __syncthreads();
        if (tid == 0) atomicExch(&g_bar1, 1);
    }
    if (tid == 0) {
        while (atomicAdd(&g_bar1, 0) == 0) __nanosleep(32);
    }
    __syncthreads();
    __threadfence();

    if (idx < n) {
        int excl = incl - v + g_partoff[b];
        off[idx] = excl;
        cur[idx] = excl;
        inv[idx] = (v > 0) ? 1.0f / (float)v : 0.0f;
    }
    if (b == 0 && tid == 0) {
        g_hoff[N_HEDGESC] = NNZC;
        g_noff[N_NODESC]  = NNZC;
    }
}

// ---------------------------------------------------------------------------
// 2. scatter edges into both CSR member lists (2 edges/thread, u16 payloads)
// ---------------------------------------------------------------------------
__global__ void __launch_bounds__(256) build_k(const int* __restrict__ ni,
                                               const int* __restrict__ hi) {
    int i = blockIdx.x * blockDim.x + threadIdx.x;
    if (2 * i >= NNZC) return;
    int2 nn = *reinterpret_cast<const int2*>(ni + 2 * i);
    int2 hh = *reinterpret_cast<const int2*>(hi + 2 * i);
    int p0 = atomicAdd(&g_hcur[hh.x], 1);
    int p1 = atomicAdd(&g_hcur[hh.y], 1);
    int q0 = atomicAdd(&g_ncur[nn.x], 1);
    int q1 = atomicAdd(&g_ncur[nn.y], 1);
    g_hlist[p0] = (unsigned short)nn.x;
    g_hlist[p1] = (unsigned short)nn.y;
    g_nlist[q0] = (unsigned short)hh.x;
    g_nlist[q1] = (unsigned short)hh.y;
}

// ---------------------------------------------------------------------------
// Gather kernels — exact R11-proven versions.
// ---------------------------------------------------------------------------

// e1h[h] = binv[h] * sum x_h[n]   (128 ch; 2 warps per hedge)
__global__ void __launch_bounds__(256) n2h1_k() {
    __shared__ float sm[4][IN_C];
    const int hloc = threadIdx.x >> 6;
    const int half = (threadIdx.x >> 5) & 1;
    const int lane = threadIdx.x & 31;
    const int h = blockIdx.x * 4 + hloc;       // grid exact: 5000/4 = 1250
    const int s = g_hoff[h], e = g_hoff[h + 1];
    const int mid = (s + e) >> 1;
    int j   = half ? mid : s;
    int end = half ? e   : mid;

    float4 a0 = make_float4(0.f, 0.f, 0.f, 0.f);
    float4 a1 = make_float4(0.f, 0.f, 0.f, 0.f);
    for (; j < end && (j & 3); j++) {
        int n0 = __ldg(g_hlist + j);
        uint2 u0 = __ldg(reinterpret_cast<const uint2*>(g_xh + n0 * IN_C) + lane);
        acc_h2(a0, u0);
    }
    for (; j + 4 <= end; j += 4) {
        uint2 idx = __ldg(reinterpret_cast<const uint2*>(g_hlist + j));
        int n0 = idx.x & 0xFFFF, n1 = idx.x >> 16;
        int n2 = idx.y & 0xFFFF, n3 = idx.y >> 16;
        uint2 u0 = __ldg(reinterpret_cast<const uint2*>(g_xh + n0 * IN_C) + lane);
        uint2 u1 = __ldg(reinterpret_cast<const uint2*>(g_xh + n1 * IN_C) + lane);
        uint2 u2 = __ldg(reinterpret_cast<const uint2*>(g_xh + n2 * IN_C) + lane);
        uint2 u3 = __ldg(reinterpret_cast<const uint2*>(g_xh + n3 * IN_C) + lane);
        acc_pair(a0, u0, u1);
        acc_pair(a1, u2, u3);
    }
    for (; j < end; j++) {
        int n0 = __ldg(g_hlist + j);
        uint2 u0 = __ldg(reinterpret_cast<const uint2*>(g_xh + n0 * IN_C) + lane);
        acc_h2(a0, u0);
    }
    float4 t;
    t.x = a0.x + a1.x; t.y = a0.y + a1.y; t.z = a0.z + a1.z; t.w = a0.w + a1.w;
    if (half == 1)
        *reinterpret_cast<float4*>(&sm[hloc][lane * 4]) = t;
    __syncthreads();
    if (half == 0) {
        float4 o = *reinterpret_cast<const float4*>(&sm[hloc][lane * 4]);
        float bi = g_binv[h];
        reinterpret_cast<uint2*>(g_e1h + h * IN_C)[lane] =
            pack_h2((t.x + o.x) * bi, (t.y + o.y) * bi,
                    (t.z + o.z) * bi, (t.w + o.w) * bi);
    }
}

// a1h[n] = dinv[n] * sum e1h[h]   (128 ch, warp per node)
__global__ void __launch_bounds__(256) h2n1_k() {
    int w = blockIdx.x * 8 + (threadIdx.x >> 5);
    if (w >= N_NODESC) return;
    int lane = threadIdx.x & 31;
    int j = g_noff[w], end = g_noff[w + 1];
    float4 a0 = make_float4(0.f, 0.f, 0.f, 0.f);
    float4 a1 = make_float4(0.f, 0.f, 0.f, 0.f);
    for (; j < end && (j & 3); j++) {
        int h0 = __ldg(g_nlist + j);
        uint2 u0 = __ldg(reinterpret_cast<const uint2*>(g_e1h + h0 * IN_C) + lane);
        acc_h2(a0, u0);
    }
    for (; j + 4 <= end; j += 4) {
        uint2 idx = __ldg(reinterpret_cast<const uint2*>(g_nlist + j));
        int h0 = idx.x & 0xFFFF, h1 = idx.x >> 16;
        int h2 = idx.y & 0xFFFF, h3 = idx.y >> 16;
        uint2 u0 = __ldg(reinterpret_cast<const uint2*>(g_e1h + h0 * IN_C) + lane);
        uint2 u1 = __ldg(reinterpret_cast<const uint2*>(g_e1h + h1 * IN_C) + lane);
        uint2 u2 = __ldg(reinterpret_cast<const uint2*>(g_e1h + h2 * IN_C) + lane);
        uint2 u3 = __ldg(reinterpret_cast<const uint2*>(g_e1h + h3 * IN_C) + lane);
        acc_pair(a0, u0, u1);
        acc_pair(a1, u2, u3);
    }
    for (; j < end; j++) {
        int h0 = __ldg(g_nlist + j);
        uint2 u0 = __ldg(reinterpret_cast<const uint2*>(g_e1h + h0 * IN_C) + lane);
        acc_h2(a0, u0);
    }
    float di = g_dinv[w];
    reinterpret_cast<uint2*>(g_a1h + w * IN_C)[lane] =
        pack_h2((a0.x + a1.x) * di, (a0.y + a1.y) * di,
                (a0.z + a1.z) * di, (a0.w + a1.w) * di);
}

// e2h[h] = binv[h] * sum y2h[n]   (64 ch; 2 x 16-lane groups per hedge)
__global__ void __launch_bounds__(256) n2h2_k() {
    __shared__ float sm[8][D2C];
    const int hloc = threadIdx.x >> 5;
    const int half = (threadIdx.x >> 4) & 1;
    const int lane = threadIdx.x & 15;
    const int h = blockIdx.x * 8 + hloc;       // grid exact: 5000/8 = 625
    const int s = g_hoff[h], e = g_hoff[h + 1];
    const int mid = (s + e) >> 1;
    int j   = half ? mid : s;
    int end = half ? e   : mid;

    float4 a0 = make_float4(0.f, 0.f, 0.f, 0.f);
    float4 a1 = make_float4(0.f, 0.f, 0.f, 0.f);
    for (; j < end && (j & 3); j++) {
        int n0 = __ldg(g_hlist + j);
        uint2 u0 = __ldg(reinterpret_cast<const uint2*>(g_y2h + n0 * D2C) + lane);
        acc_h2(a0, u0);
    }
    for (; j + 4 <= end; j += 4) {
        uint2 idx = __ldg(reinterpret_cast<const uint2*>(g_hlist + j));
        int n0 = idx.x & 0xFFFF, n1 = idx.x >> 16;
        int n2 = idx.y & 0xFFFF, n3 = idx.y >> 16;
        uint2 u0 = __ldg(reinterpret_cast<const uint2*>(g_y2h + n0 * D2C) + lane);
        uint2 u1 = __ldg(reinterpret_cast<const uint2*>(g_y2h + n1 * D2C) + lane);
        uint2 u2 = __ldg(reinterpret_cast<const uint2*>(g_y2h + n2 * D2C) + lane);
        uint2 u3 = __ldg(reinterpret_cast<const uint2*>(g_y2h + n3 * D2C) + lane);
        acc_pair(a0, u0, u1);
        acc_pair(a1, u2, u3);
    }
    for (; j < end; j++) {
        int n0 = __ldg(g_hlist + j);
        uint2 u0 = __ldg(reinterpret_cast<const uint2*>(g_y2h + n0 * D2C) + lane);
        acc_h2(a0, u0);
    }
    float4 t;
    t.x = a0.x + a1.x; t.y = a0.y + a1.y; t.z = a0.z + a1.z; t.w = a0.w + a1.w;
    if (half == 1)
        *reinterpret_cast<float4*>(&sm[hloc][lane * 4]) = t;
    __syncthreads();
    if (half == 0) {
        float4 o = *reinterpret_cast<const float4*>(&sm[hloc][lane * 4]);
        float bi = g_binv[h];
        reinterpret_cast<uint2*>(g_e2h + h * D2C)[lane] =
            pack_h2((t.x + o.x) * bi, (t.y + o.y) * bi,
                    (t.z + o.z) * bi, (t.w + o.w) * bi);
    }
}

// out[n] = relu(dinv[n] * sum e2h[h] + b2); tail restores zero-counter invariant
__global__ void __launch_bounds__(256) h2n2_k(const float* __restrict__ b2,
                                              float* __restrict__ out) {
    int g = blockIdx.x * 16 + (threadIdx.x >> 4);
    if (g < N_NODESC) {
        int lane = threadIdx.x & 15;
        int j = g_noff[g], end = g_noff[g + 1];
        float4 a0 = make_float4(0.f, 0.f, 0.f, 0.f);
        float4 a1 = make_float4(0.f, 0.f, 0.f, 0.f);
        for (; j < end && (j & 3); j++) {
            int h0 = __ldg(g_nlist + j);
            uint2 u0 = __ldg(reinterpret_cast<const uint2*>(g_e2h + h0 * D2C) + lane);
            acc_h2(a0, u0);
        }
        for (; j + 4 <= end; j += 4) {
            uint2 idx = __ldg(reinterpret_cast<const uint2*>(g_nlist + j));
            int h0 = idx.x & 0xFFFF, h1 = idx.x >> 16;
            int h2 = idx.y & 0xFFFF, h3 = idx.y >> 16;
            uint2 u0 = __ldg(reinterpret_cast<const uint2*>(g_e2h + h0 * D2C) + lane);
            uint2 u1 = __ldg(reinterpret_cast<const uint2*>(g_e2h + h1 * D2C) + lane);
            uint2 u2 = __ldg(reinterpret_cast<const uint2*>(g_e2h + h2 * D2C) + lane);
            uint2 u3 = __ldg(reinterpret_cast<const uint2*>(g_e2h + h3 * D2C) + lane);
            acc_pair(a0, u0, u1);
            acc_pair(a1, u2, u3);
        }
        for (; j < end; j++) {
            int h0 = __ldg(g_nlist + j);
            uint2 u0 = __ldg(reinterpret_cast<const uint2*>(g_e2h + h0 * D2C) + lane);
            acc_h2(a0, u0);
        }
        float di = g_dinv[g];
        float4 b = __ldg(reinterpret_cast<const float4*>(b2) + lane);
        float4 r;
        r.x = fmaxf(fmaf(a0.x + a1.x, di, b.x), 0.f);
        r.y = fmaxf(fmaf(a0.y + a1.y, di, b.y), 0.f);
        r.z = fmaxf(fmaf(a0.z + a1.z, di, b.z), 0.f);
        r.w = fmaxf(fmaf(a0.w + a1.w, di, b.w), 0.f);
        reinterpret_cast<float4*>(out + g * D2C)[lane] = r;
    }
    // restore invariant: counters zero for next launch
    int t = blockIdx.x * blockDim.x + threadIdx.x;
    int stride = gridDim.x * blockDim.x;
    for (int j = t; j < N_NODESC; j += stride) g_deg[j] = 0;
    for (int j = t; j < N_HEDGESC; j += stride) g_cnt[j] = 0;
}

// ---------------------------------------------------------------------------
// FUSED GEMM: y2 = relu(a1h @ W1 + b1) @ W2, h kept as 64x256 fp16 smem tile.
// Stage A: 64x256 tile via m16n8k16 (2x4 warps, WM=32, WN=64, 64 acc regs).
// Stage B: 64x64 = Hs @ W2^T, W2 fragments from L2-resident g_w2h.
// Hs (33.8 KB) overlaps the stage-A As/Bs buffers (25.6 KB), barrier-separated.
// ---------------------------------------------------------------------------
__device__ __forceinline__ void mma_f16(float& d0, float& d1, float& d2, float& d3,
                                        uint32_t a0, uint32_t a1, uint32_t a2, uint32_t a3,
                                        uint32_t b0, uint32_t b1) {
    asm volatile(
        "mma.sync.aligned.m16n8k16.row.col.f32.f16.f16.f32 "
        "{%0,%1,%2,%3}, {%4,%5,%6,%7}, {%8,%9}, {%0,%1,%2,%3};"
        : "+f"(d0), "+f"(d1), "+f"(d2), "+f"(d3)
        : "r"(a0), "r"(a1), "r"(a2), "r"(a3), "r"(b0), "r"(b1));
}

__global__ void __launch_bounds__(256) gemm12_k(const float* __restrict__ b1) {
    // Hs[64][264] (33792 B) overlaps As[64][40] (5120 B) + Bs[256][40] (20480 B)
    __shared__ __align__(16) unsigned char sbuf[64 * 264 * 2];
    __half (*As)[40]  = reinterpret_cast<__half(*)[40]>(sbuf);
    __half (*Bs)[40]  = reinterpret_cast<__half(*)[40]>(sbuf + 5120);
    __half (*Hs)[264] = reinterpret_cast<__half(*)[264]>(sbuf);

    const int tid  = threadIdx.x;
    const int warp = tid >> 5;
    const int lane = tid & 31;
    const int lq   = lane >> 2;
    const int lr   = lane & 3;
    const int wm   = warp >> 2;    // 0..1
    const int wn   = warp & 3;     // 0..3
    const int row0 = blockIdx.x * 64;

    // ---- Stage A: acc[2][8][4] = a1h(64x128) @ W1^T(256x128) ----
    float acc[2][8][4];
#pragma unroll
    for (int i = 0; i < 2; i++)
#pragma unroll
        for (int j = 0; j < 8; j++)
#pragma unroll
            for (int c = 0; c < 4; c++) acc[i][j][c] = 0.f;

    for (int kt = 0; kt < IN_C; kt += 32) {
        {   // load As 64x32 (1 uint4 per thread)
            int m  = tid >> 2;
            int kc = (tid & 3) * 8;
            int grow = row0 + m;
            uint4 v = make_uint4(0, 0, 0, 0);
            if (grow < N_NODESC)
                v = __ldg(reinterpret_cast<const uint4*>(g_a1h + (size_t)grow * IN_C + kt + kc));
            *reinterpret_cast<uint4*>(&As[m][kc]) = v;
        }
#pragma unroll
        for (int i = 0; i < 4; i++) {   // load Bs 256x32 (4 uint4 per thread)
            int idx = tid + i * 256;
            int n   = idx >> 2;
            int kc  = (idx & 3) * 8;
            uint4 v = __ldg(reinterpret_cast<const uint4*>(g_w1h + (size_t)n * IN_C + kt + kc));
            *reinterpret_cast<uint4*>(&Bs[n][kc]) = v;
        }
        __syncthreads();

#pragma unroll
        for (int ks = 0; ks < 32; ks += 16) {
            uint32_t af[2][4], bf[8][2];
#pragma unroll
            for (int i = 0; i < 2; i++) {
                int m0 = wm * 32 + i * 16;
                af[i][0] = *reinterpret_cast<const uint32_t*>(&As[m0 + lq    ][ks + 2 * lr    ]);
                af[i][1] = *reinterpret_cast<const uint32_t*>(&As[m0 + lq + 8][ks + 2 * lr    ]);
                af[i][2] = *reinterpret_cast<const uint32_t*>(&As[m0 + lq    ][ks + 2 * lr + 8]);
                af[i][3] = *reinterpret_cast<const uint32_t*>(&As[m0 + lq + 8][ks + 2 * lr + 8]);
            }
#pragma unroll
            for (int j = 0; j < 8; j++) {
                int n0 = wn * 64 + j * 8;
                bf[j][0] = *reinterpret_cast<const uint32_t*>(&Bs[n0 + lq][ks + 2 * lr    ]);
                bf[j][1] = *reinterpret_cast<const uint32_t*>(&Bs[n0 + lq][ks + 2 * lr + 8]);
            }
#pragma unroll
            for (int i = 0; i < 2; i++)
#pragma unroll
                for (int j = 0; j < 8; j++)
                    mma_f16(acc[i][j][0], acc[i][j][1], acc[i][j][2], acc[i][j][3],
                            af[i][0], af[i][1], af[i][2], af[i][3],
                            bf[j][0], bf[j][1]);
        }
        __syncthreads();
    }

    // ---- Stage A epilogue: relu(acc + b1) -> Hs fp16 (overwrites As/Bs) ----
#pragma unroll
    for (int i = 0; i < 2; i++) {
#pragma unroll
        for (int j = 0; j < 8; j++) {
            int r = wm * 32 + i * 16 + lq;
            int c = wn * 64 + j * 8 + 2 * lr;
            float bb0 = b1[c], bb1 = b1[c + 1];
            float v00 = fmaxf(acc[i][j][0] + bb0, 0.f);
            float v01 = fmaxf(acc[i][j][1] + bb1, 0.f);
            float v10 = fmaxf(acc[i][j][2] + bb0, 0.f);
            float v11 = fmaxf(acc[i][j][3] + bb1, 0.f);
            *reinterpret_cast<__half2*>(&Hs[r    ][c]) = __floats2half2_rn(v00, v01);
            *reinterpret_cast<__half2*>(&Hs[r + 8][c]) = __floats2half2_rn(v10, v11);
        }
    }
    __syncthreads();

    // ---- Stage B: acc2[2][2][4] = Hs(64x256) @ W2^T(64x256) -> 64x64 ----
    float acc2[2][2][4];
#pragma unroll
    for (int i = 0; i < 2; i++)
#pragma unroll
        for (int j = 0; j < 2; j++)
#pragma unroll
            for (int c = 0; c < 4; c++) acc2[i][j][c] = 0.f;

#pragma unroll 4
    for (int ks = 0; ks < D1C; ks += 16) {
        uint32_t af[2][4], bf[2][2];
#pragma unroll
        for (int i = 0; i < 2; i++) {
            int m0 = wm * 32 + i * 16;
            af[i][0] = *reinterpret_cast<const uint32_t*>(&Hs[m0 + lq    ][ks + 2 * lr    ]);
            af[i][1] = *reinterpret_cast<const uint32_t*>(&Hs[m0 + lq + 8][ks + 2 * lr    ]);
            af[i][2] = *reinterpret_cast<const uint32_t*>(&Hs[m0 + lq    ][ks + 2 * lr + 8]);
            af[i][3] = *reinterpret_cast<const uint32_t*>(&Hs[m0 + lq + 8][ks + 2 * lr + 8]);
        }
#pragma unroll
        for (int j = 0; j < 2; j++) {
            int n0 = wn * 16 + j * 8;
            bf[j][0] = __ldg(reinterpret_cast<const uint32_t*>(g_w2h + (n0 + lq) * D1C + ks + 2 * lr));
            bf[j][1] = __ldg(reinterpret_cast<const uint32_t*>(g_w2h + (n0 + lq) * D1C + ks + 2 * lr + 8));
        }
#pragma unroll
        for (int i = 0; i < 2; i++)
#pragma unroll
            for (int j = 0; j < 2; j++)
                mma_f16(acc2[i][j][0], acc2[i][j][1], acc2[i][j][2], acc2[i][j][3],
                        af[i][0], af[i][1], af[i][2], af[i][3],
                        bf[j][0], bf[j][1]);
    }

    // ---- Stage B epilogue: y2h fp16 stores ----
#pragma unroll
    for (int i = 0; i < 2; i++) {
#pragma unroll
        for (int j = 0; j < 2; j++) {
            int row = row0 + wm * 32 + i * 16 + lq;
            int col = wn * 16 + j * 8 + 2 * lr;
            if (row < N_NODESC)
                *reinterpret_cast<__half2*>(&g_y2h[(size_t)row * D2C + col]) =
                    __floats2half2_rn(acc2[i][j][0], acc2[i][j][1]);
            if (row + 8 < N_NODESC)
                *reinterpret_cast<__half2*>(&g_y2h[(size_t)(row + 8) * D2C + col]) =
                    __floats2half2_rn(acc2[i][j][2], acc2[i][j][3]);
        }
    }
}

// ---------------------------------------------------------------------------
// Launch (8 kernels)
// ---------------------------------------------------------------------------
extern "C" void kernel_launch(void* const* d_in, const int* in_sizes, int n_in,
                              void* d_out, int out_size) {
    const float* x    = (const float*)d_in[0];
    const int*   edge = (const int*)d_in[1];
    const float* W1   = (const float*)d_in[2];
    const float* b1   = (const float*)d_in[3];
    const float* W2   = (const float*)d_in[4];
    const float* b2   = (const float*)d_in[5];
    float*       out  = (float*)d_out;

    const int* ni = edge;          // edge[0] = node_idx
    const int* hi = edge + NNZC;   // edge[1] = hedge_idx

    // fused hist + conversions + barrier reset; then scan + scatter
    cvt_k<<<1024, 256>>>(x, W1, W2, ni, hi);
    scan_k<<<NBLK, 256>>>();
    build_k<<<(NNZC / 2 + 255) / 256, 256>>>(ni, hi);

    // Layer 1 aggregation at 128 channels (split hedge-side gather)
    n2h1_k<<<N_HEDGESC / 4, 256>>>();
    h2n1_k<<<(N_NODESC + 7) / 8, 256>>>();

    // y2 = relu(agg1 @ W1 + b1) @ W2 — fused, h stays in smem
    gemm12_k<<<(N_NODESC + 63) / 64, 256>>>(b1);

    // Layer 2 aggregation at 64 channels (split hedge-side gather) + epilogue
    n2h2_k<<<N_HEDGESC / 8, 256>>>();
    h2n2_k<<<(N_NODESC + 15) / 16, 256>>>(b2, out);
}

// round 15
// speedup vs baseline: 1.0677x; 1.0148x over previous
#include <cuda_runtime.h>
#include <cuda_fp16.h>
#include <cstdint>
#include <cstddef>

// Problem constants (fixed shapes for Hgnn_17394617548829)
#define N_NODESC 50000
#define N_HEDGESC 5000
#define NNZC 800000
#define IN_C 128
#define D1C 256
#define D2C 64

// Scan chunking: 256 elements per block
#define NBLK_H 20    // ceil(5000/256)
#define NBLK_N 196   // ceil(50000/256)
#define NBLK   216

// ---------------------------------------------------------------------------
// Scratch (static device globals; no allocation anywhere).
// INVARIANT: g_deg / g_cnt are all-zero at kernel_launch entry.
//   - first run: .bss zero-initialization
//   - later runs: zeroed at the tail of h2n2_k (last kernel of previous run)
// ---------------------------------------------------------------------------
__device__ __align__(16) __half g_xh  [(size_t)N_NODESC * IN_C];   // 12.8 MB
__device__ __align__(16) __half g_e1h [(size_t)N_HEDGESC * IN_C];  // 1.28 MB
__device__ __align__(16) __half g_a1h [(size_t)N_NODESC * IN_C];   // 12.8 MB
__device__ __align__(16) __half g_hh  [(size_t)N_NODESC * D1C];    // 25.6 MB
__device__ __align__(16) __half g_y2h [(size_t)N_NODESC * D2C];    // 6.4 MB
__device__ __align__(16) __half g_e2h [(size_t)N_HEDGESC * D2C];   // 0.64 MB
__device__ __align__(16) __half g_w1h [(size_t)D1C * IN_C];        // W1^T [256][128]
__device__ __align__(16) __half g_w2h [(size_t)D2C * D1C];         // W2^T [64][256]
__device__ int   g_cnt [N_HEDGESC];
__device__ int   g_deg [N_NODESC];
__device__ int   g_hoff[N_HEDGESC + 1];
__device__ int   g_noff[N_NODESC + 1];
__device__ int   g_hcur[N_HEDGESC];
__device__ int   g_ncur[N_NODESC];
__device__ __align__(16) unsigned short g_hlist[NNZC];             // node ids
__device__ __align__(16) unsigned short g_nlist[NNZC];             // hedge ids
__device__ float g_dinv[N_NODESC];
__device__ float g_binv[N_HEDGESC];
__device__ int   g_part[NBLK];
__device__ int   g_partoff[NBLK];
__device__ int   g_bar0;            // grid-barrier counters (reset in cvt_k)
__device__ int   g_bar1;

// ---------------------------------------------------------------------------
// fp16 helpers
// ---------------------------------------------------------------------------
__device__ __forceinline__ void acc_h2(float4& a, uint2 u) {
    float2 f0 = __half22float2(*reinterpret_cast<__half2*>(&u.x));
    float2 f1 = __half22float2(*reinterpret_cast<__half2*>(&u.y));
    a.x += f0.x; a.y += f0.y; a.z += f1.x; a.w += f1.y;
}

// Pairwise fp16 combine (HADD2), then fp32 accumulate.
__device__ __forceinline__ void acc_pair(float4& a, uint2 u0, uint2 u1) {
    __half2 sx = __hadd2(*reinterpret_cast<__half2*>(&u0.x),
                         *reinterpret_cast<__half2*>(&u1.x));
    __half2 sy = __hadd2(*reinterpret_cast<__half2*>(&u0.y),
                         *reinterpret_cast<__half2*>(&u1.y));
    float2 fx = __half22float2(sx);
    float2 fy = __half22float2(sy);
    a.x += fx.x; a.y += fx.y; a.z += fy.x; a.w += fy.y;
}

__device__ __forceinline__ uint2 pack_h2(float x, float y, float z, float w) {
    __half2 h0 = __floats2half2_rn(x, y);
    __half2 h1 = __floats2half2_rn(z, w);
    uint2 u;
    u.x = *reinterpret_cast<unsigned*>(&h0);
    u.y = *reinterpret_cast<unsigned*>(&h1);
    return u;
}

// ---------------------------------------------------------------------------
// 0. FUSED: degree histograms (fire-and-forget REDs) + fp16 conversions +
//    grid-barrier reset.
// ---------------------------------------------------------------------------
__global__ void __launch_bounds__(256) cvt_k(const float* __restrict__ x,
                                             const float* __restrict__ W1,
                                             const float* __restrict__ W2,
                                             const int* __restrict__ ni,
                                             const int* __restrict__ hi) {
    int i = blockIdx.x * blockDim.x + threadIdx.x;
    int stride = gridDim.x * blockDim.x;
    if (i == 0) { g_bar0 = 0; g_bar1 = 0; }

    for (int j = i; j < NNZC / 2; j += stride) {
        int2 nn = *reinterpret_cast<const int2*>(ni + 2 * j);
        int2 hh = *reinterpret_cast<const int2*>(hi + 2 * j);
        atomicAdd(&g_deg[nn.x], 1);
        atomicAdd(&g_deg[nn.y], 1);
        atomicAdd(&g_cnt[hh.x], 1);
        atomicAdd(&g_cnt[hh.y], 1);
    }

    const float4* x4 = reinterpret_cast<const float4*>(x);
    uint2* xh2 = reinterpret_cast<uint2*>(g_xh);
    for (int j = i; j < N_NODESC * IN_C / 4; j += stride) {
        float4 v = x4[j];
        xh2[j] = pack_h2(v.x, v.y, v.z, v.w);
    }
    for (int j = i; j < D1C * IN_C; j += stride) {
        int n = j / IN_C, k = j % IN_C;
        g_w1h[j] = __float2half(W1[(size_t)k * D1C + n]);
    }
    for (int j = i; j < D2C * D1C; j += stride) {
        int n = j / D1C, k = j % D1C;
        g_w2h[j] = __float2half(W2[(size_t)k * D2C + n]);
    }
}

// ---------------------------------------------------------------------------
// 1. fused segmented exclusive scan (grid barrier; phase 2 in block-0 smem)
// ---------------------------------------------------------------------------
__global__ void __launch_bounds__(256) scan_k() {
    __shared__ int sh[256];
    __shared__ int shp[NBLK];
    const int b   = blockIdx.x;
    const int tid = threadIdx.x;
    const int* src; int* off; int* cur; float* inv;
    int idx, n;
    if (b < NBLK_H) {
        src = g_cnt; off = g_hoff; cur = g_hcur; inv = g_binv;
        idx = b * 256 + tid; n = N_HEDGESC;
    } else {
        src = g_deg; off = g_noff; cur = g_ncur; inv = g_dinv;
        idx = (b - NBLK_H) * 256 + tid; n = N_NODESC;
    }
    int v = (idx < n) ? src[idx] : 0;

    sh[tid] = v;
    __syncthreads();
    for (int d = 1; d < 256; d <<= 1) {
        int t = (tid >= d) ? sh[tid - d] : 0;
        __syncthreads();
        sh[tid] += t;
        __syncthreads();
    }
    int incl = sh[tid];
    if (tid == 255) {
        g_part[b] = incl;
        __threadfence();
        atomicAdd(&g_bar0, 1);
    }

    if (b == 0) {
        if (tid == 0) {
            while (atomicAdd(&g_bar0, 0) < NBLK) __nanosleep(32);
        }
        __syncthreads();
        __threadfence();
        if (tid < NBLK) shp[tid] = g_part[tid];
        __syncthreads();
        if (tid == 0) {
            int run = 0;
            for (int i = 0; i < NBLK_H; i++) { int c = shp[i]; shp[i] = run; run += c; }
            run = 0;
            for (int i = NBLK_H; i < NBLK; i++) { int c = shp[i]; shp[i] = run; run += c; }
        }
        __syncthreads();
        if (tid < NBLK) g_partoff[tid] = shp[tid];
        __threadfence();
        __syncthreads();
        if (tid == 0) atomicExch(&g_bar1, 1);
    }
    if (tid == 0) {
        while (atomicAdd(&g_bar1, 0) == 0) __nanosleep(32);
    }
    __syncthreads();
    __threadfence();

    if (idx < n) {
        int excl = incl - v + g_partoff[b];
        off[idx] = excl;
        cur[idx] = excl;
        inv[idx] = (v > 0) ? 1.0f / (float)v : 0.0f;
    }
    if (b == 0 && tid == 0) {
        g_hoff[N_HEDGESC] = NNZC;
        g_noff[N_NODESC]  = NNZC;
    }
}

// ---------------------------------------------------------------------------
// 2. scatter edges into both CSR member lists.
//    1 edge/thread (800k threads): maximizes chip-wide outstanding ATOMG MLP —
//    measured faster than 2 edges/thread (28.9 vs 31.4 us).
// ---------------------------------------------------------------------------
__global__ void __launch_bounds__(256) build_k(const int* __restrict__ ni,
                                               const int* __restrict__ hi) {
    int i = blockIdx.x * blockDim.x + threadIdx.x;
    if (i >= NNZC) return;
    int n = __ldg(ni + i);
    int h = __ldg(hi + i);
    int p = atomicAdd(&g_hcur[h], 1);
    int q = atomicAdd(&g_ncur[n], 1);
    g_hlist[p] = (unsigned short)n;
    g_nlist[q] = (unsigned short)h;
}

// ---------------------------------------------------------------------------
// Gather kernels — exact R11-proven versions (167.0 us config).
// ---------------------------------------------------------------------------

// e1h[h] = binv[h] * sum x_h[n]   (128 ch; 2 warps per hedge)
__global__ void __launch_bounds__(256) n2h1_k() {
    __shared__ float sm[4][IN_C];
    const int hloc = threadIdx.x >> 6;
    const int half = (threadIdx.x >> 5) & 1;
    const int lane = threadIdx.x & 31;
    const int h = blockIdx.x * 4 + hloc;       // grid exact: 5000/4 = 1250
    const int s = g_hoff[h], e = g_hoff[h + 1];
    const int mid = (s + e) >> 1;
    int j   = half ? mid : s;
    int end = half ? e   : mid;

    float4 a0 = make_float4(0.f, 0.f, 0.f, 0.f);
    float4 a1 = make_float4(0.f, 0.f, 0.f, 0.f);
    for (; j < end && (j & 3); j++) {
        int n0 = __ldg(g_hlist + j);
        uint2 u0 = __ldg(reinterpret_cast<const uint2*>(g_xh + n0 * IN_C) + lane);
        acc_h2(a0, u0);
    }
    for (; j + 4 <= end; j += 4) {
        uint2 idx = __ldg(reinterpret_cast<const uint2*>(g_hlist + j));
        int n0 = idx.x & 0xFFFF, n1 = idx.x >> 16;
        int n2 = idx.y & 0xFFFF, n3 = idx.y >> 16;
        uint2 u0 = __ldg(reinterpret_cast<const uint2*>(g_xh + n0 * IN_C) + lane);
        uint2 u1 = __ldg(reinterpret_cast<const uint2*>(g_xh + n1 * IN_C) + lane);
        uint2 u2 = __ldg(reinterpret_cast<const uint2*>(g_xh + n2 * IN_C) + lane);
        uint2 u3 = __ldg(reinterpret_cast<const uint2*>(g_xh + n3 * IN_C) + lane);
        acc_pair(a0, u0, u1);
        acc_pair(a1, u2, u3);
    }
    for (; j < end; j++) {
        int n0 = __ldg(g_hlist + j);
        uint2 u0 = __ldg(reinterpret_cast<const uint2*>(g_xh + n0 * IN_C) + lane);
        acc_h2(a0, u0);
    }
    float4 t;
    t.x = a0.x + a1.x; t.y = a0.y + a1.y; t.z = a0.z + a1.z; t.w = a0.w + a1.w;
    if (half == 1)
        *reinterpret_cast<float4*>(&sm[hloc][lane * 4]) = t;
    __syncthreads();
    if (half == 0) {
        float4 o = *reinterpret_cast<const float4*>(&sm[hloc][lane * 4]);
        float bi = g_binv[h];
        reinterpret_cast<uint2*>(g_e1h + h * IN_C)[lane] =
            pack_h2((t.x + o.x) * bi, (t.y + o.y) * bi,
                    (t.z + o.z) * bi, (t.w + o.w) * bi);
    }
}

// a1h[n] = dinv[n] * sum e1h[h]   (128 ch, warp per node)
__global__ void __launch_bounds__(256) h2n1_k() {
    int w = blockIdx.x * 8 + (threadIdx.x >> 5);
    if (w >= N_NODESC) return;
    int lane = threadIdx.x & 31;
    int j = g_noff[w], end = g_noff[w + 1];
    float4 a0 = make_float4(0.f, 0.f, 0.f, 0.f);
    float4 a1 = make_float4(0.f, 0.f, 0.f, 0.f);
    for (; j < end && (j & 3); j++) {
        int h0 = __ldg(g_nlist + j);
        uint2 u0 = __ldg(reinterpret_cast<const uint2*>(g_e1h + h0 * IN_C) + lane);
        acc_h2(a0, u0);
    }
    for (; j + 4 <= end; j += 4) {
        uint2 idx = __ldg(reinterpret_cast<const uint2*>(g_nlist + j));
        int h0 = idx.x & 0xFFFF, h1 = idx.x >> 16;
        int h2 = idx.y & 0xFFFF, h3 = idx.y >> 16;
        uint2 u0 = __ldg(reinterpret_cast<const uint2*>(g_e1h + h0 * IN_C) + lane);
        uint2 u1 = __ldg(reinterpret_cast<const uint2*>(g_e1h + h1 * IN_C) + lane);
        uint2 u2 = __ldg(reinterpret_cast<const uint2*>(g_e1h + h2 * IN_C) + lane);
        uint2 u3 = __ldg(reinterpret_cast<const uint2*>(g_e1h + h3 * IN_C) + lane);
        acc_pair(a0, u0, u1);
        acc_pair(a1, u2, u3);
    }
    for (; j < end; j++) {
        int h0 = __ldg(g_nlist + j);
        uint2 u0 = __ldg(reinterpret_cast<const uint2*>(g_e1h + h0 * IN_C) + lane);
        acc_h2(a0, u0);
    }
    float di = g_dinv[w];
    reinterpret_cast<uint2*>(g_a1h + w * IN_C)[lane] =
        pack_h2((a0.x + a1.x) * di, (a0.y + a1.y) * di,
                (a0.z + a1.z) * di, (a0.w + a1.w) * di);
}

// e2h[h] = binv[h] * sum y2h[n]   (64 ch; 2 x 16-lane groups per hedge)
__global__ void __launch_bounds__(256) n2h2_k() {
    __shared__ float sm[8][D2C];
    const int hloc = threadIdx.x >> 5;
    const int half = (threadIdx.x >> 4) & 1;
    const int lane = threadIdx.x & 15;
    const int h = blockIdx.x * 8 + hloc;       // grid exact: 5000/8 = 625
    const int s = g_hoff[h], e = g_hoff[h + 1];
    const int mid = (s + e) >> 1;
    int j   = half ? mid : s;
    int end = half ? e   : mid;

    float4 a0 = make_float4(0.f, 0.f, 0.f, 0.f);
    float4 a1 = make_float4(0.f, 0.f, 0.f, 0.f);
    for (; j < end && (j & 3); j++) {
        int n0 = __ldg(g_hlist + j);
        uint2 u0 = __ldg(reinterpret_cast<const uint2*>(g_y2h + n0 * D2C) + lane);
        acc_h2(a0, u0);
    }
    for (; j + 4 <= end; j += 4) {
        uint2 idx = __ldg(reinterpret_cast<const uint2*>(g_hlist + j));
        int n0 = idx.x & 0xFFFF, n1 = idx.x >> 16;
        int n2 = idx.y & 0xFFFF, n3 = idx.y >> 16;
        uint2 u0 = __ldg(reinterpret_cast<const uint2*>(g_y2h + n0 * D2C) + lane);
        uint2 u1 = __ldg(reinterpret_cast<const uint2*>(g_y2h + n1 * D2C) + lane);
        uint2 u2 = __ldg(reinterpret_cast<const uint2*>(g_y2h + n2 * D2C) + lane);
        uint2 u3 = __ldg(reinterpret_cast<const uint2*>(g_y2h + n3 * D2C) + lane);
        acc_pair(a0, u0, u1);
        acc_pair(a1, u2, u3);
    }
    for (; j < end; j++) {
        int n0 = __ldg(g_hlist + j);
        uint2 u0 = __ldg(reinterpret_cast<const uint2*>(g_y2h + n0 * D2C) + lane);
        acc_h2(a0, u0);
    }
    float4 t;
    t.x = a0.x + a1.x; t.y = a0.y + a1.y; t.z = a0.z + a1.z; t.w = a0.w + a1.w;
    if (half == 1)
        *reinterpret_cast<float4*>(&sm[hloc][lane * 4]) = t;
    __syncthreads();
    if (half == 0) {
        float4 o = *reinterpret_cast<const float4*>(&sm[hloc][lane * 4]);
        float bi = g_binv[h];
        reinterpret_cast<uint2*>(g_e2h + h * D2C)[lane] =
            pack_h2((t.x + o.x) * bi, (t.y + o.y) * bi,
                    (t.z + o.z) * bi, (t.w + o.w) * bi);
    }
}

// out[n] = relu(dinv[n] * sum e2h[h] + b2); tail restores zero-counter invariant
__global__ void __launch_bounds__(256) h2n2_k(const float* __restrict__ b2,
                                              float* __restrict__ out) {
    int g = blockIdx.x * 16 + (threadIdx.x >> 4);
    if (g < N_NODESC) {
        int lane = threadIdx.x & 15;
        int j = g_noff[g], end = g_noff[g + 1];
        float4 a0 = make_float4(0.f, 0.f, 0.f, 0.f);
        float4 a1 = make_float4(0.f, 0.f, 0.f, 0.f);
        for (; j < end && (j & 3); j++) {
            int h0 = __ldg(g_nlist + j);
            uint2 u0 = __ldg(reinterpret_cast<const uint2*>(g_e2h + h0 * D2C) + lane);
            acc_h2(a0, u0);
        }
        for (; j + 4 <= end; j += 4) {
            uint2 idx = __ldg(reinterpret_cast<const uint2*>(g_nlist + j));
            int h0 = idx.x & 0xFFFF, h1 = idx.x >> 16;
            int h2 = idx.y & 0xFFFF, h3 = idx.y >> 16;
            uint2 u0 = __ldg(reinterpret_cast<const uint2*>(g_e2h + h0 * D2C) + lane);
            uint2 u1 = __ldg(reinterpret_cast<const uint2*>(g_e2h + h1 * D2C) + lane);
            uint2 u2 = __ldg(reinterpret_cast<const uint2*>(g_e2h + h2 * D2C) + lane);
            uint2 u3 = __ldg(reinterpret_cast<const uint2*>(g_e2h + h3 * D2C) + lane);
            acc_pair(a0, u0, u1);
            acc_pair(a1, u2, u3);
        }
        for (; j < end; j++) {
            int h0 = __ldg(g_nlist + j);
            uint2 u0 = __ldg(reinterpret_cast<const uint2*>(g_e2h + h0 * D2C) + lane);
            acc_h2(a0, u0);
        }
        float di = g_dinv[g];
        float4 b = __ldg(reinterpret_cast<const float4*>(b2) + lane);
        float4 r;
        r.x = fmaxf(fmaf(a0.x + a1.x, di, b.x), 0.f);
        r.y = fmaxf(fmaf(a0.y + a1.y, di, b.y), 0.f);
        r.z = fmaxf(fmaf(a0.z + a1.z, di, b.z), 0.f);
        r.w = fmaxf(fmaf(a0.w + a1.w, di, b.w), 0.f);
        reinterpret_cast<float4*>(out + g * D2C)[lane] = r;
    }
    // restore invariant: counters zero for next launch
    int t = blockIdx.x * blockDim.x + threadIdx.x;
    int stride = gridDim.x * blockDim.x;
    for (int j = t; j < N_NODESC; j += stride) g_deg[j] = 0;
    for (int j = t; j < N_HEDGESC; j += stride) g_cnt[j] = 0;
}

// ---------------------------------------------------------------------------
// fp16 tensor-core GEMM (R6 verified; split gemm1/gemm2 — the 167.0 config).
// ---------------------------------------------------------------------------
__device__ __forceinline__ void mma_f16(float& d0, float& d1, float& d2, float& d3,
                                        uint32_t a0, uint32_t a1, uint32_t a2, uint32_t a3,
                                        uint32_t b0, uint32_t b1) {
    asm volatile(
        "mma.sync.aligned.m16n8k16.row.col.f32.f16.f16.f32 "
        "{%0,%1,%2,%3}, {%4,%5,%6,%7}, {%8,%9}, {%0,%1,%2,%3};"
        : "+f"(d0), "+f"(d1), "+f"(d2), "+f"(d3)
        : "r"(a0), "r"(a1), "r"(a2), "r"(a3), "r"(b0), "r"(b1));
}

template <int BM, int BN, int BK, int WARPS_M, int WARPS_N, bool EPI>
__device__ __forceinline__ void gemm_f16_body(const __half* __restrict__ A,
                                              const __half* __restrict__ Bt,
                                              const float* __restrict__ bias,
                                              __half* __restrict__ C,
                                              int M, int N, int K) {
    constexpr int THREADS = WARPS_M * WARPS_N * 32;
    constexpr int WM = BM / WARPS_M;
    constexpr int WN = BN / WARPS_N;
    constexpr int MI = WM / 16;
    constexpr int NI = WN / 8;
    constexpr int PAD = 8;
    constexpr int AV = (BM * BK / 8) / THREADS;
    constexpr int BV = (BN * BK / 8) / THREADS;

    __shared__ __align__(16) __half As[BM][BK + PAD];
    __shared__ __align__(16) __half Bs[BN][BK + PAD];

    const int tid  = threadIdx.x;
    const int warp = tid >> 5;
    const int lane = tid & 31;
    const int wm   = warp / WARPS_N;
    const int wn   = warp % WARPS_N;
    const int row0 = blockIdx.y * BM;
    const int col0 = blockIdx.x * BN;
    const int lq   = lane >> 2;
    const int lr   = lane & 3;

    float acc[MI][NI][4];
#pragma unroll
    for (int i = 0; i < MI; i++)
#pragma unroll
        for (int j = 0; j < NI; j++)
#pragma unroll
            for (int c = 0; c < 4; c++) acc[i][j][c] = 0.f;

    for (int kt = 0; kt < K; kt += BK) {
#pragma unroll
        for (int i = 0; i < AV; i++) {
            int idx = tid + i * THREADS;
            int m   = idx / (BK / 8);
            int kc  = (idx % (BK / 8)) * 8;
            int grow = row0 + m;
            uint4 v = make_uint4(0, 0, 0, 0);
            if (grow < M)
                v = __ldg(reinterpret_cast<const uint4*>(A + (size_t)grow * K + kt + kc));
            *reinterpret_cast<uint4*>(&As[m][kc]) = v;
        }
#pragma unroll
        for (int i = 0; i < BV; i++) {
            int idx = tid + i * THREADS;
            int n   = idx / (BK / 8);
            int kc  = (idx % (BK / 8)) * 8;
            uint4 v = __ldg(reinterpret_cast<const uint4*>(Bt + (size_t)(col0 + n) * K + kt + kc));
            *reinterpret_cast<uint4*>(&Bs[n][kc]) = v;
        }
        __syncthreads();

#pragma unroll
        for (int ks = 0; ks < BK; ks += 16) {
            uint32_t af[MI][4];
            uint32_t bf[NI][2];
#pragma unroll
            for (int i = 0; i < MI; i++) {
                int m0 = wm * WM + i * 16;
                af[i][0] = *reinterpret_cast<const uint32_t*>(&As[m0 + lq    ][ks + 2 * lr    ]);
                af[i][1] = *reinterpret_cast<const uint32_t*>(&As[m0 + lq + 8][ks + 2 * lr    ]);
                af[i][2] = *reinterpret_cast<const uint32_t*>(&As[m0 + lq    ][ks + 2 * lr + 8]);
                af[i][3] = *reinterpret_cast<const uint32_t*>(&As[m0 + lq + 8][ks + 2 * lr + 8]);
            }
#pragma unroll
            for (int j = 0; j < NI; j++) {
                int n0 = wn * WN + j * 8;
                bf[j][0] = *reinterpret_cast<const uint32_t*>(&Bs[n0 + lq][ks + 2 * lr    ]);
                bf[j][1] = *reinterpret_cast<const uint32_t*>(&Bs[n0 + lq][ks + 2 * lr + 8]);
            }
#pragma unroll
            for (int i = 0; i < MI; i++)
#pragma unroll
                for (int j = 0; j < NI; j++)
                    mma_f16(acc[i][j][0], acc[i][j][1], acc[i][j][2], acc[i][j][3],
                            af[i][0], af[i][1], af[i][2], af[i][3],
                            bf[j][0], bf[j][1]);
        }
        __syncthreads();
    }

#pragma unroll
    for (int i = 0; i < MI; i++) {
#pragma unroll
        for (int j = 0; j < NI; j++) {
            int row = row0 + wm * WM + i * 16 + lq;
            int col = col0 + wn * WN + j * 8 + 2 * lr;
            float2 v0 = make_float2(acc[i][j][0], acc[i][j][1]);
            float2 v1 = make_float2(acc[i][j][2], acc[i][j][3]);
            if (EPI) {
                float b0 = bias[col], b1 = bias[col + 1];
                v0.x = fmaxf(v0.x + b0, 0.f);
                v0.y = fmaxf(v0.y + b1, 0.f);
                v1.x = fmaxf(v1.x + b0, 0.f);
                v1.y = fmaxf(v1.y + b1, 0.f);
            }
            if (row < M)
                *reinterpret_cast<__half2*>(&C[(size_t)row * N + col]) =
                    __floats2half2_rn(v0.x, v0.y);
            if (row + 8 < M)
                *reinterpret_cast<__half2*>(&C[(size_t)(row + 8) * N + col]) =
                    __floats2half2_rn(v1.x, v1.y);
        }
    }
}

// GEMM1: g_hh = relu(g_a1h @ W1 + b1)   [50000x128]@[128x256]
__global__ void __launch_bounds__(256) gemm1_k(const float* __restrict__ b1) {
    gemm_f16_body<128, 128, 32, 2, 4, true>(g_a1h, g_w1h, b1, g_hh, N_NODESC, D1C, IN_C);
}

// GEMM2: g_y2h = g_hh @ W2   [50000x256]@[256x64]
__global__ void __launch_bounds__(256) gemm2_k() {
    gemm_f16_body<128, 64, 32, 4, 2, false>(g_hh, g_w2h, nullptr, g_y2h, N_NODESC, D2C, D1C);
}

// ---------------------------------------------------------------------------
// Launch (9 kernels)
// ---------------------------------------------------------------------------
extern "C" void kernel_launch(void* const* d_in, const int* in_sizes, int n_in,
                              void* d_out, int out_size) {
    const float* x    = (const float*)d_in[0];
    const int*   edge = (const int*)d_in[1];
    const float* W1   = (const float*)d_in[2];
    const float* b1   = (const float*)d_in[3];
    const float* W2   = (const float*)d_in[4];
    const float* b2   = (const float*)d_in[5];
    float*       out  = (float*)d_out;

    const int* ni = edge;          // edge[0] = node_idx
    const int* hi = edge + NNZC;   // edge[1] = hedge_idx

    // fused hist + conversions + barrier reset; then scan + scatter
    cvt_k<<<1024, 256>>>(x, W1, W2, ni, hi);
    scan_k<<<NBLK, 256>>>();
    build_k<<<(NNZC + 255) / 256, 256>>>(ni, hi);

    // Layer 1 aggregation at 128 channels (split hedge-side gather)
    n2h1_k<<<N_HEDGESC / 4, 256>>>();
    h2n1_k<<<(N_NODESC + 7) / 8, 256>>>();

    // h = relu(agg1 @ W1 + b1) ; y2 = h @ W2   (fp16 tensor cores)
    {
        dim3 g1(D1C / 128, (N_NODESC + 127) / 128);
        gemm1_k<<<g1, 256>>>(b1);
        dim3 g2(D2C / 64, (N_NODESC + 127) / 128);
        gemm2_k<<<g2, 256>>>();
    }

    // Layer 2 aggregation at 64 channels (split hedge-side gather) + epilogue
    n2h2_k<<<N_HEDGESC / 8, 256>>>();
    h2n2_k<<<(N_NODESC + 15) / 16, 256>>>(b2, out);
}

// round 16
// speedup vs baseline: 1.0789x; 1.0105x over previous
#include <cuda_runtime.h>
#include <cuda_fp16.h>
#include <cstdint>
#include <cstddef>

// Problem constants (fixed shapes for Hgnn_17394617548829)
#define N_NODESC 50000
#define N_HEDGESC 5000
#define NNZC 800000
#define IN_C 128
#define D1C 256
#define D2C 64

// Scan chunking: 256 elements per block
#define NBLK_H 20    // ceil(5000/256)
#define NBLK_N 196   // ceil(50000/256)
#define NBLK   216

// n2h1 fused grid split
#define N2H1_BLKS (N_HEDGESC / 4)              // 1250 gather blocks
#define BLDN_BLKS ((NNZC + 255) / 256)         // 3125 nlist-scatter blocks

// ---------------------------------------------------------------------------
// Scratch (static device globals; no allocation anywhere).
// INVARIANT: g_deg / g_cnt are all-zero at kernel_launch entry.
// ---------------------------------------------------------------------------
__device__ __align__(16) __half g_xh  [(size_t)N_NODESC * IN_C];   // 12.8 MB
__device__ __align__(16) __half g_e1h [(size_t)N_HEDGESC * IN_C];  // 1.28 MB
__device__ __align__(16) __half g_a1h [(size_t)N_NODESC * IN_C];   // 12.8 MB
__device__ __align__(16) __half g_hh  [(size_t)N_NODESC * D1C];    // 25.6 MB
__device__ __align__(16) __half g_y2h [(size_t)N_NODESC * D2C];    // 6.4 MB
__device__ __align__(16) __half g_e2h [(size_t)N_HEDGESC * D2C];   // 0.64 MB
__device__ __align__(16) __half g_w1h [(size_t)D1C * IN_C];        // W1^T [256][128]
__device__ __align__(16) __half g_w2h [(size_t)D2C * D1C];         // W2^T [64][256]
__device__ int   g_cnt [N_HEDGESC];
__device__ int   g_deg [N_NODESC];
__device__ int   g_hoff[N_HEDGESC + 1];
__device__ int   g_noff[N_NODESC + 1];
__device__ int   g_hcur[N_HEDGESC];
__device__ int   g_ncur[N_NODESC];
__device__ __align__(16) unsigned short g_hlist[NNZC];             // node ids
__device__ __align__(16) unsigned short g_nlist[NNZC];             // hedge ids
__device__ float g_dinv[N_NODESC];
__device__ float g_binv[N_HEDGESC];
__device__ int   g_part[NBLK];
__device__ int   g_partoff[NBLK];
__device__ int   g_bar0;            // grid-barrier counters (reset in cvt_k)
__device__ int   g_bar1;

// ---------------------------------------------------------------------------
// fp16 helpers
// ---------------------------------------------------------------------------
__device__ __forceinline__ void acc_h2(float4& a, uint2 u) {
    float2 f0 = __half22float2(*reinterpret_cast<__half2*>(&u.x));
    float2 f1 = __half22float2(*reinterpret_cast<__half2*>(&u.y));
    a.x += f0.x; a.y += f0.y; a.z += f1.x; a.w += f1.y;
}

// Pairwise fp16 combine (HADD2), then fp32 accumulate.
__device__ __forceinline__ void acc_pair(float4& a, uint2 u0, uint2 u1) {
    __half2 sx = __hadd2(*reinterpret_cast<__half2*>(&u0.x),
                         *reinterpret_cast<__half2*>(&u1.x));
    __half2 sy = __hadd2(*reinterpret_cast<__half2*>(&u0.y),
                         *reinterpret_cast<__half2*>(&u1.y));
    float2 fx = __half22float2(sx);
    float2 fy = __half22float2(sy);
    a.x += fx.x; a.y += fx.y; a.z += fy.x; a.w += fy.y;
}

__device__ __forceinline__ uint2 pack_h2(float x, float y, float z, float w) {
    __half2 h0 = __floats2half2_rn(x, y);
    __half2 h1 = __floats2half2_rn(z, w);
    uint2 u;
    u.x = *reinterpret_cast<unsigned*>(&h0);
    u.y = *reinterpret_cast<unsigned*>(&h1);
    return u;
}

// ---------------------------------------------------------------------------
// 0. FUSED: degree histograms (fire-and-forget REDs) + fp16 conversions +
//    grid-barrier reset.
// ---------------------------------------------------------------------------
__global__ void __launch_bounds__(256) cvt_k(const float* __restrict__ x,
                                             const float* __restrict__ W1,
                                             const float* __restrict__ W2,
                                             const int* __restrict__ ni,
                                             const int* __restrict__ hi) {
    int i = blockIdx.x * blockDim.x + threadIdx.x;
    int stride = gridDim.x * blockDim.x;
    if (i == 0) { g_bar0 = 0; g_bar1 = 0; }

    for (int j = i; j < NNZC / 2; j += stride) {
        int2 nn = *reinterpret_cast<const int2*>(ni + 2 * j);
        int2 hh = *reinterpret_cast<const int2*>(hi + 2 * j);
        atomicAdd(&g_deg[nn.x], 1);
        atomicAdd(&g_deg[nn.y], 1);
        atomicAdd(&g_cnt[hh.x], 1);
        atomicAdd(&g_cnt[hh.y], 1);
    }

    const float4* x4 = reinterpret_cast<const float4*>(x);
    uint2* xh2 = reinterpret_cast<uint2*>(g_xh);
    for (int j = i; j < N_NODESC * IN_C / 4; j += stride) {
        float4 v = x4[j];
        xh2[j] = pack_h2(v.x, v.y, v.z, v.w);
    }
    for (int j = i; j < D1C * IN_C; j += stride) {
        int n = j / IN_C, k = j % IN_C;
        g_w1h[j] = __float2half(W1[(size_t)k * D1C + n]);
    }
    for (int j = i; j < D2C * D1C; j += stride) {
        int n = j / D1C, k = j % D1C;
        g_w2h[j] = __float2half(W2[(size_t)k * D2C + n]);
    }
}

// ---------------------------------------------------------------------------
// 1. fused segmented exclusive scan (grid barrier; phase 2 in block-0 smem)
// ---------------------------------------------------------------------------
__global__ void __launch_bounds__(256) scan_k() {
    __shared__ int sh[256];
    __shared__ int shp[NBLK];
    const int b   = blockIdx.x;
    const int tid = threadIdx.x;
    const int* src; int* off; int* cur; float* inv;
    int idx, n;
    if (b < NBLK_H) {
        src = g_cnt; off = g_hoff; cur = g_hcur; inv = g_binv;
        idx = b * 256 + tid; n = N_HEDGESC;
    } else {
        src = g_deg; off = g_noff; cur = g_ncur; inv = g_dinv;
        idx = (b - NBLK_H) * 256 + tid; n = N_NODESC;
    }
    int v = (idx < n) ? src[idx] : 0;

    sh[tid] = v;
    __syncthreads();
    for (int d = 1; d < 256; d <<= 1) {
        int t = (tid >= d) ? sh[tid - d] : 0;
        __syncthreads();
        sh[tid] += t;
        __syncthreads();
    }
    int incl = sh[tid];
    if (tid == 255) {
        g_part[b] = incl;
        __threadfence();
        atomicAdd(&g_bar0, 1);
    }

    if (b == 0) {
        if (tid == 0) {
            while (atomicAdd(&g_bar0, 0) < NBLK) __nanosleep(32);
        }
        __syncthreads();
        __threadfence();
        if (tid < NBLK) shp[tid] = g_part[tid];
        __syncthreads();
        if (tid == 0) {
            int run = 0;
            for (int i = 0; i < NBLK_H; i++) { int c = shp[i]; shp[i] = run; run += c; }
            run = 0;
            for (int i = NBLK_H; i < NBLK; i++) { int c = shp[i]; shp[i] = run; run += c; }
        }
        __syncthreads();
        if (tid < NBLK) g_partoff[tid] = shp[tid];
        __threadfence();
        __syncthreads();
        if (tid == 0) atomicExch(&g_bar1, 1);
    }
    if (tid == 0) {
        while (atomicAdd(&g_bar1, 0) == 0) __nanosleep(32);
    }
    __syncthreads();
    __threadfence();

    if (idx < n) {
        int excl = incl - v + g_partoff[b];
        off[idx] = excl;
        cur[idx] = excl;
        inv[idx] = (v > 0) ? 1.0f / (float)v : 0.0f;
    }
    if (b == 0 && tid == 0) {
        g_hoff[N_HEDGESC] = NNZC;
        g_noff[N_NODESC]  = NNZC;
    }
}

// ---------------------------------------------------------------------------
// 2. scatter edges into the HEDGE-major list only (1 edge/thread — max MLP).
//    The node-major scatter is fused into n2h1_k below (it is only needed
//    by h2n1_k, which runs after n2h1_k).
// ---------------------------------------------------------------------------
__global__ void __launch_bounds__(256) build_h_k(const int* __restrict__ ni,
                                                 const int* __restrict__ hi) {
    int i = blockIdx.x * blockDim.x + threadIdx.x;
    if (i >= NNZC) return;
    int n = __ldg(ni + i);
    int h = __ldg(hi + i);
    int p = atomicAdd(&g_hcur[h], 1);
    g_hlist[p] = (unsigned short)n;
}

// ---------------------------------------------------------------------------
// 3. FUSED: n2h1 gather (blocks [0, N2H1_BLKS)) + nlist scatter (rest).
//    The ATOMG-latency-bound scatter hides under the L2-bound gather.
// ---------------------------------------------------------------------------
// e1h[h] = binv[h] * sum x_h[n]   (128 ch; 2 warps per hedge)
__global__ void __launch_bounds__(256) n2h1_k(const int* __restrict__ ni,
                                              const int* __restrict__ hi) {
    if (blockIdx.x >= N2H1_BLKS) {
        // ---- nlist scatter: 1 edge per thread ----
        int i = (blockIdx.x - N2H1_BLKS) * 256 + threadIdx.x;
        if (i < NNZC) {
            int n = __ldg(ni + i);
            int h = __ldg(hi + i);
            int q = atomicAdd(&g_ncur[n], 1);
            g_nlist[q] = (unsigned short)h;
        }
        return;
    }

    __shared__ float sm[4][IN_C];
    const int hloc = threadIdx.x >> 6;
    const int half = (threadIdx.x >> 5) & 1;
    const int lane = threadIdx.x & 31;
    const int h = blockIdx.x * 4 + hloc;       // grid exact: 5000/4 = 1250
    const int s = g_hoff[h], e = g_hoff[h + 1];
    const int mid = (s + e) >> 1;
    int j   = half ? mid : s;
    int end = half ? e   : mid;

    float4 a0 = make_float4(0.f, 0.f, 0.f, 0.f);
    float4 a1 = make_float4(0.f, 0.f, 0.f, 0.f);
    for (; j < end && (j & 3); j++) {
        int n0 = __ldg(g_hlist + j);
        uint2 u0 = __ldg(reinterpret_cast<const uint2*>(g_xh + n0 * IN_C) + lane);
        acc_h2(a0, u0);
    }
    for (; j + 4 <= end; j += 4) {
        uint2 idx = __ldg(reinterpret_cast<const uint2*>(g_hlist + j));
        int n0 = idx.x & 0xFFFF, n1 = idx.x >> 16;
        int n2 = idx.y & 0xFFFF, n3 = idx.y >> 16;
        uint2 u0 = __ldg(reinterpret_cast<const uint2*>(g_xh + n0 * IN_C) + lane);
        uint2 u1 = __ldg(reinterpret_cast<const uint2*>(g_xh + n1 * IN_C) + lane);
        uint2 u2 = __ldg(reinterpret_cast<const uint2*>(g_xh + n2 * IN_C) + lane);
        uint2 u3 = __ldg(reinterpret_cast<const uint2*>(g_xh + n3 * IN_C) + lane);
        acc_pair(a0, u0, u1);
        acc_pair(a1, u2, u3);
    }
    for (; j < end; j++) {
        int n0 = __ldg(g_hlist + j);
        uint2 u0 = __ldg(reinterpret_cast<const uint2*>(g_xh + n0 * IN_C) + lane);
        acc_h2(a0, u0);
    }
    float4 t;
    t.x = a0.x + a1.x; t.y = a0.y + a1.y; t.z = a0.z + a1.z; t.w = a0.w + a1.w;
    if (half == 1)
        *reinterpret_cast<float4*>(&sm[hloc][lane * 4]) = t;
    __syncthreads();
    if (half == 0) {
        float4 o = *reinterpret_cast<const float4*>(&sm[hloc][lane * 4]);
        float bi = g_binv[h];
        reinterpret_cast<uint2*>(g_e1h + h * IN_C)[lane] =
            pack_h2((t.x + o.x) * bi, (t.y + o.y) * bi,
                    (t.z + o.z) * bi, (t.w + o.w) * bi);
    }
}

// a1h[n] = dinv[n] * sum e1h[h]   (128 ch, warp per node)
__global__ void __launch_bounds__(256) h2n1_k() {
    int w = blockIdx.x * 8 + (threadIdx.x >> 5);
    if (w >= N_NODESC) return;
    int lane = threadIdx.x & 31;
    int j = g_noff[w], end = g_noff[w + 1];
    float4 a0 = make_float4(0.f, 0.f, 0.f, 0.f);
    float4 a1 = make_float4(0.f, 0.f, 0.f, 0.f);
    for (; j < end && (j & 3); j++) {
        int h0 = __ldg(g_nlist + j);
        uint2 u0 = __ldg(reinterpret_cast<const uint2*>(g_e1h + h0 * IN_C) + lane);
        acc_h2(a0, u0);
    }
    for (; j + 4 <= end; j += 4) {
        uint2 idx = __ldg(reinterpret_cast<const uint2*>(g_nlist + j));
        int h0 = idx.x & 0xFFFF, h1 = idx.x >> 16;
        int h2 = idx.y & 0xFFFF, h3 = idx.y >> 16;
        uint2 u0 = __ldg(reinterpret_cast<const uint2*>(g_e1h + h0 * IN_C) + lane);
        uint2 u1 = __ldg(reinterpret_cast<const uint2*>(g_e1h + h1 * IN_C) + lane);
        uint2 u2 = __ldg(reinterpret_cast<const uint2*>(g_e1h + h2 * IN_C) + lane);
        uint2 u3 = __ldg(reinterpret_cast<const uint2*>(g_e1h + h3 * IN_C) + lane);
        acc_pair(a0, u0, u1);
        acc_pair(a1, u2, u3);
    }
    for (; j < end; j++) {
        int h0 = __ldg(g_nlist + j);
        uint2 u0 = __ldg(reinterpret_cast<const uint2*>(g_e1h + h0 * IN_C) + lane);
        acc_h2(a0, u0);
    }
    float di = g_dinv[w];
    reinterpret_cast<uint2*>(g_a1h + w * IN_C)[lane] =
        pack_h2((a0.x + a1.x) * di, (a0.y + a1.y) * di,
                (a0.z + a1.z) * di, (a0.w + a1.w) * di);
}

// e2h[h] = binv[h] * sum y2h[n]   (64 ch; 2 x 16-lane groups per hedge)
__global__ void __launch_bounds__(256) n2h2_k() {
    __shared__ float sm[8][D2C];
    const int hloc = threadIdx.x >> 5;
    const int half = (threadIdx.x >> 4) & 1;
    const int lane = threadIdx.x & 15;
    const int h = blockIdx.x * 8 + hloc;       // grid exact: 5000/8 = 625
    const int s = g_hoff[h], e = g_hoff[h + 1];
    const int mid = (s + e) >> 1;
    int j   = half ? mid : s;
    int end = half ? e   : mid;

    float4 a0 = make_float4(0.f, 0.f, 0.f, 0.f);
    float4 a1 = make_float4(0.f, 0.f, 0.f, 0.f);
    for (; j < end && (j & 3); j++) {
        int n0 = __ldg(g_hlist + j);
        uint2 u0 = __ldg(reinterpret_cast<const uint2*>(g_y2h + n0 * D2C) + lane);
        acc_h2(a0, u0);
    }
    for (; j + 4 <= end; j += 4) {
        uint2 idx = __ldg(reinterpret_cast<const uint2*>(g_hlist + j));
        int n0 = idx.x & 0xFFFF, n1 = idx.x >> 16;
        int n2 = idx.y & 0xFFFF, n3 = idx.y >> 16;
        uint2 u0 = __ldg(reinterpret_cast<const uint2*>(g_y2h + n0 * D2C) + lane);
        uint2 u1 = __ldg(reinterpret_cast<const uint2*>(g_y2h + n1 * D2C) + lane);
        uint2 u2 = __ldg(reinterpret_cast<const uint2*>(g_y2h + n2 * D2C) + lane);
        uint2 u3 = __ldg(reinterpret_cast<const uint2*>(g_y2h + n3 * D2C) + lane);
        acc_pair(a0, u0, u1);
        acc_pair(a1, u2, u3);
    }
    for (; j < end; j++) {
        int n0 = __ldg(g_hlist + j);
        uint2 u0 = __ldg(reinterpret_cast<const uint2*>(g_y2h + n0 * D2C) + lane);
        acc_h2(a0, u0);
    }
    float4 t;
    t.x = a0.x + a1.x; t.y = a0.y + a1.y; t.z = a0.z + a1.z; t.w = a0.w + a1.w;
    if (half == 1)
        *reinterpret_cast<float4*>(&sm[hloc][lane * 4]) = t;
    __syncthreads();
    if (half == 0) {
        float4 o = *reinterpret_cast<const float4*>(&sm[hloc][lane * 4]);
        float bi = g_binv[h];
        reinterpret_cast<uint2*>(g_e2h + h * D2C)[lane] =
            pack_h2((t.x + o.x) * bi, (t.y + o.y) * bi,
                    (t.z + o.z) * bi, (t.w + o.w) * bi);
    }
}

// out[n] = relu(dinv[n] * sum e2h[h] + b2); tail restores zero-counter invariant
__global__ void __launch_bounds__(256) h2n2_k(const float* __restrict__ b2,
                                              float* __restrict__ out) {
    int g = blockIdx.x * 16 + (threadIdx.x >> 4);
    if (g < N_NODESC) {
        int lane = threadIdx.x & 15;
        int j = g_noff[g], end = g_noff[g + 1];
        float4 a0 = make_float4(0.f, 0.f, 0.f, 0.f);
        float4 a1 = make_float4(0.f, 0.f, 0.f, 0.f);
        for (; j < end && (j & 3); j++) {
            int h0 = __ldg(g_nlist + j);
            uint2 u0 = __ldg(reinterpret_cast<const uint2*>(g_e2h + h0 * D2C) + lane);
            acc_h2(a0, u0);
        }
        for (; j + 4 <= end; j += 4) {
            uint2 idx = __ldg(reinterpret_cast<const uint2*>(g_nlist + j));
            int h0 = idx.x & 0xFFFF, h1 = idx.x >> 16;
            int h2 = idx.y & 0xFFFF, h3 = idx.y >> 16;
            uint2 u0 = __ldg(reinterpret_cast<const uint2*>(g_e2h + h0 * D2C) + lane);
            uint2 u1 = __ldg(reinterpret_cast<const uint2*>(g_e2h + h1 * D2C) + lane);
            uint2 u2 = __ldg(reinterpret_cast<const uint2*>(g_e2h + h2 * D2C) + lane);
            uint2 u3 = __ldg(reinterpret_cast<const uint2*>(g_e2h + h3 * D2C) + lane);
            acc_pair(a0, u0, u1);
            acc_pair(a1, u2, u3);
        }
        for (; j < end; j++) {
            int h0 = __ldg(g_nlist + j);
            uint2 u0 = __ldg(reinterpret_cast<const uint2*>(g_e2h + h0 * D2C) + lane);
            acc_h2(a0, u0);
        }
        float di = g_dinv[g];
        float4 b = __ldg(reinterpret_cast<const float4*>(b2) + lane);
        float4 r;
        r.x = fmaxf(fmaf(a0.x + a1.x, di, b.x), 0.f);
        r.y = fmaxf(fmaf(a0.y + a1.y, di, b.y), 0.f);
        r.z = fmaxf(fmaf(a0.z + a1.z, di, b.z), 0.f);
        r.w = fmaxf(fmaf(a0.w + a1.w, di, b.w), 0.f);
        reinterpret_cast<float4*>(out + g * D2C)[lane] = r;
    }
    // restore invariant: counters zero for next launch
    int t = blockIdx.x * blockDim.x + threadIdx.x;
    int stride = gridDim.x * blockDim.x;
    for (int j = t; j < N_NODESC; j += stride) g_deg[j] = 0;
    for (int j = t; j < N_HEDGESC; j += stride) g_cnt[j] = 0;
}

// ---------------------------------------------------------------------------
// fp16 tensor-core GEMM (R6 verified; split gemm1/gemm2).
// ---------------------------------------------------------------------------
__device__ __forceinline__ void mma_f16(float& d0, float& d1, float& d2, float& d3,
                                        uint32_t a0, uint32_t a1, uint32_t a2, uint32_t a3,
                                        uint32_t b0, uint32_t b1) {
    asm volatile(
        "mma.sync.aligned.m16n8k16.row.col.f32.f16.f16.f32 "
        "{%0,%1,%2,%3}, {%4,%5,%6,%7}, {%8,%9}, {%0,%1,%2,%3};"
        : "+f"(d0), "+f"(d1), "+f"(d2), "+f"(d3)
        : "r"(a0), "r"(a1), "r"(a2), "r"(a3), "r"(b0), "r"(b1));
}

template <int BM, int BN, int BK, int WARPS_M, int WARPS_N, bool EPI>
__device__ __forceinline__ void gemm_f16_body(const __half* __restrict__ A,
                                              const __half* __restrict__ Bt,
                                              const float* __restrict__ bias,
                                              __half* __restrict__ C,
                                              int M, int N, int K) {
    constexpr int THREADS = WARPS_M * WARPS_N * 32;
    constexpr int WM = BM / WARPS_M;
    constexpr int WN = BN / WARPS_N;
    constexpr int MI = WM / 16;
    constexpr int NI = WN / 8;
    constexpr int PAD = 8;
    constexpr int AV = (BM * BK / 8) / THREADS;
    constexpr int BV = (BN * BK / 8) / THREADS;

    __shared__ __align__(16) __half As[BM][BK + PAD];
    __shared__ __align__(16) __half Bs[BN][BK + PAD];

    const int tid  = threadIdx.x;
    const int warp = tid >> 5;
    const int lane = tid & 31;
    const int wm   = warp / WARPS_N;
    const int wn   = warp % WARPS_N;
    const int row0 = blockIdx.y * BM;
    const int col0 = blockIdx.x * BN;
    const int lq   = lane >> 2;
    const int lr   = lane & 3;

    float acc[MI][NI][4];
#pragma unroll
    for (int i = 0; i < MI; i++)
#pragma unroll
        for (int j = 0; j < NI; j++)
#pragma unroll
            for (int c = 0; c < 4; c++) acc[i][j][c] = 0.f;

    for (int kt = 0; kt < K; kt += BK) {
#pragma unroll
        for (int i = 0; i < AV; i++) {
            int idx = tid + i * THREADS;
            int m   = idx / (BK / 8);
            int kc  = (idx % (BK / 8)) * 8;
            int grow = row0 + m;
            uint4 v = make_uint4(0, 0, 0, 0);
            if (grow < M)
                v = __ldg(reinterpret_cast<const uint4*>(A + (size_t)grow * K + kt + kc));
            *reinterpret_cast<uint4*>(&As[m][kc]) = v;
        }
#pragma unroll
        for (int i = 0; i < BV; i++) {
            int idx = tid + i * THREADS;
            int n   = idx / (BK / 8);
            int kc  = (idx % (BK / 8)) * 8;
            uint4 v = __ldg(reinterpret_cast<const uint4*>(Bt + (size_t)(col0 + n) * K + kt + kc));
            *reinterpret_cast<uint4*>(&Bs[n][kc]) = v;
        }
        __syncthreads();

#pragma unroll
        for (int ks = 0; ks < BK; ks += 16) {
            uint32_t af[MI][4];
            uint32_t bf[NI][2];
#pragma unroll
            for (int i = 0; i < MI; i++) {
                int m0 = wm * WM + i * 16;
                af[i][0] = *reinterpret_cast<const uint32_t*>(&As[m0 + lq    ][ks + 2 * lr    ]);
                af[i][1] = *reinterpret_cast<const uint32_t*>(&As[m0 + lq + 8][ks + 2 * lr    ]);
                af[i][2] = *reinterpret_cast<const uint32_t*>(&As[m0 + lq    ][ks + 2 * lr + 8]);
                af[i][3] = *reinterpret_cast<const uint32_t*>(&As[m0 + lq + 8][ks + 2 * lr + 8]);
            }
#pragma unroll
            for (int j = 0; j < NI; j++) {
                int n0 = wn * WN + j * 8;
                bf[j][0] = *reinterpret_cast<const uint32_t*>(&Bs[n0 + lq][ks + 2 * lr    ]);
                bf[j][1] = *reinterpret_cast<const uint32_t*>(&Bs[n0 + lq][ks + 2 * lr + 8]);
            }
#pragma unroll
            for (int i = 0; i < MI; i++)
#pragma unroll
                for (int j = 0; j < NI; j++)
                    mma_f16(acc[i][j][0], acc[i][j][1], acc[i][j][2], acc[i][j][3],
                            af[i][0], af[i][1], af[i][2], af[i][3],
                            bf[j][0], bf[j][1]);
        }
        __syncthreads();
    }

#pragma unroll
    for (int i = 0; i < MI; i++) {
#pragma unroll
        for (int j = 0; j < NI; j++) {
            int row = row0 + wm * WM + i * 16 + lq;
            int col = col0 + wn * WN + j * 8 + 2 * lr;
            float2 v0 = make_float2(acc[i][j][0], acc[i][j][1]);
            float2 v1 = make_float2(acc[i][j][2], acc[i][j][3]);
            if (EPI) {
                float b0 = bias[col], b1 = bias[col + 1];
                v0.x = fmaxf(v0.x + b0, 0.f);
                v0.y = fmaxf(v0.y + b1, 0.f);
                v1.x = fmaxf(v1.x + b0, 0.f);
                v1.y = fmaxf(v1.y + b1, 0.f);
            }
            if (row < M)
                *reinterpret_cast<__half2*>(&C[(size_t)row * N + col]) =
                    __floats2half2_rn(v0.x, v0.y);
            if (row + 8 < M)
                *reinterpret_cast<__half2*>(&C[(size_t)(row + 8) * N + col]) =
                    __floats2half2_rn(v1.x, v1.y);
        }
    }
}

// GEMM1: g_hh = relu(g_a1h @ W1 + b1)   [50000x128]@[128x256]
__global__ void __launch_bounds__(256) gemm1_k(const float* __restrict__ b1) {
    gemm_f16_body<128, 128, 32, 2, 4, true>(g_a1h, g_w1h, b1, g_hh, N_NODESC, D1C, IN_C);
}

// GEMM2: g_y2h = g_hh @ W2   [50000x256]@[256x64]
__global__ void __launch_bounds__(256) gemm2_k() {
    gemm_f16_body<128, 64, 32, 4, 2, false>(g_hh, g_w2h, nullptr, g_y2h, N_NODESC, D2C, D1C);
}

// ---------------------------------------------------------------------------
// Launch (9 kernels; nlist scatter hidden inside n2h1)
// ---------------------------------------------------------------------------
extern "C" void kernel_launch(void* const* d_in, const int* in_sizes, int n_in,
                              void* d_out, int out_size) {
    const float* x    = (const float*)d_in[0];
    const int*   edge = (const int*)d_in[1];
    const float* W1   = (const float*)d_in[2];
    const float* b1   = (const float*)d_in[3];
    const float* W2   = (const float*)d_in[4];
    const float* b2   = (const float*)d_in[5];
    float*       out  = (float*)d_out;

    const int* ni = edge;          // edge[0] = node_idx
    const int* hi = edge + NNZC;   // edge[1] = hedge_idx

    // fused hist + conversions + barrier reset; scan; hlist scatter
    cvt_k<<<1024, 256>>>(x, W1, W2, ni, hi);
    scan_k<<<NBLK, 256>>>();
    build_h_k<<<(NNZC + 255) / 256, 256>>>(ni, hi);

    // Layer 1 hedge gather + (overlapped) nlist scatter; then node gather
    n2h1_k<<<N2H1_BLKS + BLDN_BLKS, 256>>>(ni, hi);
    h2n1_k<<<(N_NODESC + 7) / 8, 256>>>();

    // h = relu(agg1 @ W1 + b1) ; y2 = h @ W2   (fp16 tensor cores)
    {
        dim3 g1(D1C / 128, (N_NODESC + 127) / 128);
        gemm1_k<<<g1, 256>>>(b1);
        dim3 g2(D2C / 64, (N_NODESC + 127) / 128);
        gemm2_k<<<g2, 256>>>();
    }

    // Layer 2 aggregation at 64 channels (split hedge-side gather) + epilogue
    n2h2_k<<<N_HEDGESC / 8, 256>>>();
    h2n2_k<<<(N_NODESC + 15) / 16, 256>>>(b2, out);
}